// round 2
// baseline (speedup 1.0000x reference)
#include <cuda_runtime.h>
#include <cuda_bf16.h>
#include <cstddef>

// ---------------------------------------------------------------------------
// RSFM = 2x conv1x1 in  ->  6x fused (rmsnorm + mamba-style block + residual)
//        -> conv1x1 out.   h-update is ELEMENT-WISE over L (no scan); only the
//        depthwise conv1d couples neighboring positions (halo = 1).
// Shapes: B=2, L=4096, d_model=64, d_inner=128, d_state=16, dt_rank=32.
// Output = concat(ravel(conv3_out [2,64,64,64]), ravel(h [2,4096,128,16])).
// ---------------------------------------------------------------------------

#define LSEQ   4096
#define DM     64
#define DI     128
#define DS     16
#define TT     24                    // interior positions per tile
#define TPB_   171                   // tiles per batch: 170*24 + 16
#define NTILES (2 * TPB_)
#define CONV_OUT_ELEMS (2 * 64 * LSEQ)   // 524288

// shared memory layout (float offsets), total 55616 floats = 222464 B
#define OFF_WIN 0        // in_proj^T  [k=64][o=256]
#define OFF_WX  16384    // x_proj^T   [d=128][o=64]
#define OFF_WDT 24576    // dt_proj^T  [r=32][d=128]
#define OFF_WO  28672    // out_proj^T [d=128][c=64]
#define OFF_AS  36864    // A=-exp(A_log), padded [128][17]
#define OFF_CW  39040    // conv1d w [t=3][d=128]
#define OFF_CB  39424
#define OFF_DTB 39552
#define OFF_DP  39680
#define OFF_NW  39808
#define OFF_XN  39872    // rmsnormed input [26][64]
#define OFF_XCR 41536    // raw xc (pre-conv) [26][128]
#define OFF_SZ  44864    // silu(z) [24][128]
#define OFF_XC  47936    // conv+silu xc; later gated y [24][128]
#define OFF_DL  51008    // delta [24][128]
#define OFF_DBC 54080    // x_proj out [24][64]
#define SMEM_FLOATS 55616
#define SMEM_BYTES  (SMEM_FLOATS * 4)

// persistent scratch (device globals; no runtime allocation)
__device__ float g_rgb [2 * LSEQ * DM];
__device__ float g_dte [2 * LSEQ * DM];
__device__ float g_bufA[2 * LSEQ * DM];
__device__ float g_bufB[2 * LSEQ * DM];
__device__ float g_h   [(size_t)2 * LSEQ * DI * DS];   // 64 MB

__device__ __forceinline__ float sigmoidf_(float x) { return 1.f / (1.f + __expf(-x)); }

// ---------------------------------------------------------------------------
// input conv1x1: out[b,l,o] = sum_c x[b,c,l] * w[o,c] + bias[o]
// ---------------------------------------------------------------------------
__global__ __launch_bounds__(256) void conv_in_kernel(
    const float* __restrict__ x, const float* __restrict__ w,
    const float* __restrict__ bias, int which)
{
    __shared__ float xs[64 * 64];   // [cin][p]
    __shared__ float wt[64 * 64];   // [cin][o]
    __shared__ float bs[64];
    float* out = which ? g_dte : g_rgb;

    const int tile = blockIdx.x;      // 128 tiles: b = tile>>6, 64 positions each
    const int b  = tile >> 6;
    const int l0 = (tile & 63) << 6;
    const int tid = threadIdx.x;

    for (int i = tid; i < 4096; i += 256) { int o = i >> 6, c = i & 63; wt[c * 64 + o] = w[i]; }
    if (tid < 64) bs[tid] = bias[tid];
    for (int i = tid; i < 4096; i += 256) {
        int c = i >> 6, p = i & 63;
        xs[i] = x[((size_t)b * 64 + c) * LSEQ + l0 + p];
    }
    __syncthreads();

    const int pg = tid >> 6;          // 4 position groups
    const int o  = tid & 63;
    for (int p = pg; p < 64; p += 4) {
        float acc = bs[o];
        #pragma unroll 8
        for (int c = 0; c < 64; c++) acc = fmaf(xs[c * 64 + p], wt[c * 64 + o], acc);
        out[((size_t)b * LSEQ + l0 + p) * DM + o] = acc;
    }
}

// ---------------------------------------------------------------------------
// final conv1x1: d_out[b,o,l] = sum_c bufB[b,l,c] * w[o,c] + bias[o]  (NCHW)
// ---------------------------------------------------------------------------
__global__ __launch_bounds__(256) void conv_out_kernel(
    const float* __restrict__ w, const float* __restrict__ bias, float* __restrict__ out)
{
    __shared__ float xs[64 * 65];   // [p][c] padded
    __shared__ float ws[64 * 64];   // [o][c]
    __shared__ float bs[64];

    const int tile = blockIdx.x;
    const int b  = tile >> 6;
    const int l0 = (tile & 63) << 6;
    const int tid = threadIdx.x;

    for (int i = tid; i < 4096; i += 256) ws[i] = w[i];
    if (tid < 64) bs[tid] = bias[tid];
    for (int i = tid; i < 4096; i += 256) {
        int p = i >> 6, c = i & 63;
        xs[p * 65 + c] = g_bufB[((size_t)b * LSEQ + l0 + p) * DM + c];
    }
    __syncthreads();

    const int wid = tid >> 5, lane = tid & 31;
    for (int o = wid; o < 64; o += 8)
        for (int p = lane; p < 64; p += 32) {
            float acc = bs[o];
            #pragma unroll 8
            for (int c = 0; c < 64; c++) acc = fmaf(xs[p * 65 + c], ws[o * 64 + c], acc);
            out[((size_t)b * 64 + o) * LSEQ + l0 + p] = acc;
        }
}

// ---------------------------------------------------------------------------
// One fused residual block.
// ---------------------------------------------------------------------------
__global__ __launch_bounds__(256, 1) void rsfm_block_kernel(
    int kblk,
    const float* __restrict__ inpw, const float* __restrict__ cvw, const float* __restrict__ cvb,
    const float* __restrict__ xpw,  const float* __restrict__ dtw, const float* __restrict__ dtb,
    const float* __restrict__ alog, const float* __restrict__ dpw, const float* __restrict__ opw,
    const float* __restrict__ normw, float* __restrict__ h_final)
{
    extern __shared__ float sm[];
    const int tid  = threadIdx.x;
    const int wid  = tid >> 5, lane = tid & 31;

    // ---- load weights (transposed for coalesced matvec reads) ----
    for (int i = tid; i < 256 * 64; i += 256) { int o = i >> 6, k = i & 63;  sm[OFF_WIN + k * 256 + o] = inpw[i]; }
    for (int i = tid; i < 64 * 128; i += 256) { int o = i >> 7, d = i & 127; sm[OFF_WX  + d * 64  + o] = xpw[i]; }
    for (int i = tid; i < 128 * 32; i += 256) { int d = i >> 5, r = i & 31;  sm[OFF_WDT + r * 128 + d] = dtw[i]; }
    for (int i = tid; i < 64 * 128; i += 256) { int c = i >> 7, d = i & 127; sm[OFF_WO  + d * 64  + c] = opw[i]; }
    for (int i = tid; i < 128 * 16; i += 256) { int d = i >> 4, s = i & 15;  sm[OFF_AS + d * 17 + s] = -__expf(alog[i]); }
    for (int i = tid; i < 384; i += 256)      { int d = i / 3, t = i % 3;    sm[OFF_CW + t * 128 + d] = cvw[i]; }
    if (tid < 128) { sm[OFF_CB + tid] = cvb[tid]; sm[OFF_DTB + tid] = dtb[tid]; sm[OFF_DP + tid] = dpw[tid]; }
    if (tid < 64)  sm[OFF_NW + tid] = normw[tid];
    __syncthreads();

    const float* base  = (kblk & 1) ? g_dte : g_rgb;
    const float* prevp = (kblk == 0) ? (const float*)0 : ((kblk & 1) ? g_bufA : g_bufB);
    float*       outb  = (kblk & 1) ? g_bufB : g_bufA;
    const bool   rd_h  = (kblk != 0);
    float*       hout  = (kblk == 5) ? h_final : g_h;

    const int tile = blockIdx.x;
    const int b    = tile / TPB_;
    const int l0   = (tile - b * TPB_) * TT;
    const int cnt  = (TT < LSEQ - l0) ? TT : (LSEQ - l0);     // 24 or 16 (even)
    const int ne   = cnt + 2;

    // ---- Stage A: (base + prev) -> rmsnorm -> XN[ne][64] ----
    for (int t = wid; t < ne; t += 8) {
        int l = l0 - 1 + t;
        float x0 = 0.f, x1 = 0.f;
        if (l >= 0 && l < LSEQ) {
            size_t off = ((size_t)b * LSEQ + l) * DM;
            x0 = base[off + lane]; x1 = base[off + lane + 32];
            if (prevp) { x0 += prevp[off + lane]; x1 += prevp[off + lane + 32]; }
        }
        float ss = x0 * x0 + x1 * x1;
        #pragma unroll
        for (int o = 16; o; o >>= 1) ss += __shfl_xor_sync(0xffffffffu, ss, o);
        float inv = rsqrtf(ss * (1.f / 64.f) + 1e-5f);
        sm[OFF_XN + t * 64 + lane]      = x0 * inv * sm[OFF_NW + lane];
        sm[OFF_XN + t * 64 + lane + 32] = x1 * inv * sm[OFF_NW + lane + 32];
    }
    __syncthreads();

    // ---- Stage B: in_proj 64->256.  xc_raw for all slots; silu(z) interior ----
    for (int idx = tid; idx < ne * 64; idx += 256) {
        int t = idx >> 6, og = (idx & 63) << 2;
        float a0 = 0.f, a1 = 0.f, a2 = 0.f, a3 = 0.f;
        const float* xn = &sm[OFF_XN + t * 64];
        #pragma unroll 8
        for (int k = 0; k < 64; k++) {
            float x = xn[k];
            float4 w = *(const float4*)&sm[OFF_WIN + k * 256 + og];
            a0 = fmaf(x, w.x, a0); a1 = fmaf(x, w.y, a1);
            a2 = fmaf(x, w.z, a2); a3 = fmaf(x, w.w, a3);
        }
        if (og < 128) {
            *(float4*)&sm[OFF_XCR + t * 128 + og] = make_float4(a0, a1, a2, a3);
        } else if (t >= 1 && t <= cnt) {
            int zi = (t - 1) * 128 + og - 128;
            sm[OFF_SZ + zi + 0] = a0 * sigmoidf_(a0);
            sm[OFF_SZ + zi + 1] = a1 * sigmoidf_(a1);
            sm[OFF_SZ + zi + 2] = a2 * sigmoidf_(a2);
            sm[OFF_SZ + zi + 3] = a3 * sigmoidf_(a3);
        }
    }
    __syncthreads();

    // ---- Stage C: depthwise conv1d (k=3, pad 1) + silu -> XC[cnt][128] ----
    for (int idx = tid; idx < cnt * 128; idx += 256) {
        int ti = idx >> 7, d = idx & 127;
        float v = sm[OFF_CB + d];
        v = fmaf(sm[OFF_CW +       d], sm[OFF_XCR +  ti      * 128 + d], v);
        v = fmaf(sm[OFF_CW + 128 + d], sm[OFF_XCR + (ti + 1) * 128 + d], v);
        v = fmaf(sm[OFF_CW + 256 + d], sm[OFF_XCR + (ti + 2) * 128 + d], v);
        sm[OFF_XC + idx] = v * sigmoidf_(v);
    }
    __syncthreads();

    // ---- Stage D: x_proj 128->64 -> DBC[cnt][64]  (2 pos x 2 out per thread) ----
    for (int idx = tid; idx < (cnt >> 1) * 32; idx += 256) {
        int ti0 = (idx >> 5) << 1, op = (idx & 31) << 1;
        float a00 = 0.f, a01 = 0.f, a10 = 0.f, a11 = 0.f;
        const float* x0 = &sm[OFF_XC +  ti0      * 128];
        const float* x1 = &sm[OFF_XC + (ti0 + 1) * 128];
        #pragma unroll 8
        for (int d = 0; d < 128; d++) {
            float2 w = *(const float2*)&sm[OFF_WX + d * 64 + op];
            float v0 = x0[d], v1 = x1[d];
            a00 = fmaf(v0, w.x, a00); a01 = fmaf(v0, w.y, a01);
            a10 = fmaf(v1, w.x, a10); a11 = fmaf(v1, w.y, a11);
        }
        *(float2*)&sm[OFF_DBC +  ti0      * 64 + op] = make_float2(a00, a01);
        *(float2*)&sm[OFF_DBC + (ti0 + 1) * 64 + op] = make_float2(a10, a11);
    }
    __syncthreads();

    // ---- Stage E: dt_proj 32->128 + bias + softplus -> DL[cnt][128] ----
    for (int idx = tid; idx < (cnt >> 1) * 64; idx += 256) {
        int ti0 = (idx >> 6) << 1, dp = (idx & 63) << 1;
        float a00 = sm[OFF_DTB + dp], a01 = sm[OFF_DTB + dp + 1];
        float a10 = a00, a11 = a01;
        const float* r0 = &sm[OFF_DBC +  ti0      * 64];
        const float* r1 = &sm[OFF_DBC + (ti0 + 1) * 64];
        #pragma unroll
        for (int r = 0; r < 32; r++) {
            float2 w = *(const float2*)&sm[OFF_WDT + r * 128 + dp];
            float v0 = r0[r], v1 = r1[r];
            a00 = fmaf(v0, w.x, a00); a01 = fmaf(v0, w.y, a01);
            a10 = fmaf(v1, w.x, a10); a11 = fmaf(v1, w.y, a11);
        }
        sm[OFF_DL +  ti0      * 128 + dp]     = (a00 > 20.f) ? a00 : log1pf(__expf(a00));
        sm[OFF_DL +  ti0      * 128 + dp + 1] = (a01 > 20.f) ? a01 : log1pf(__expf(a01));
        sm[OFF_DL + (ti0 + 1) * 128 + dp]     = (a10 > 20.f) ? a10 : log1pf(__expf(a10));
        sm[OFF_DL + (ti0 + 1) * 128 + dp + 1] = (a11 > 20.f) ? a11 : log1pf(__expf(a11));
    }
    __syncthreads();

    // ---- Stage F: SSM h-update + y + gating.  XC[idx] := y * silu(z) ----
    for (int idx = tid; idx < cnt * 128; idx += 256) {
        int ti = idx >> 7, d = idx & 127;
        size_t hix = (((size_t)b * LSEQ + l0 + ti) * DI + d) * DS;
        float delta = sm[OFF_DL + idx];
        float xc    = sm[OFF_XC + idx];
        float dx    = delta * xc;
        const float* Bs = &sm[OFF_DBC + ti * 64 + 32];
        const float* Cs = &sm[OFF_DBC + ti * 64 + 48];
        const float* Ar = &sm[OFF_AS + d * 17];
        float4 ho[4];
        if (rd_h) {
            const float4* hp = (const float4*)(g_h + hix);
            ho[0] = hp[0]; ho[1] = hp[1]; ho[2] = hp[2]; ho[3] = hp[3];
        } else {
            ho[0] = ho[1] = ho[2] = ho[3] = make_float4(0.f, 0.f, 0.f, 0.f);
        }
        float y = 0.f;
        float4 hn[4];
        #pragma unroll
        for (int q = 0; q < 4; q++) {
            float* hv = (float*)&hn[q];
            const float* hov = (const float*)&ho[q];
            #pragma unroll
            for (int j = 0; j < 4; j++) {
                int s = q * 4 + j;
                float v = fmaf(__expf(delta * Ar[s]), hov[j], dx * Bs[s]);
                hv[j] = v;
                y = fmaf(v, Cs[s], y);
            }
        }
        float4* hw = (float4*)(hout + hix);
        hw[0] = hn[0]; hw[1] = hn[1]; hw[2] = hn[2]; hw[3] = hn[3];
        y = fmaf(sm[OFF_DP + d], xc, y);
        sm[OFF_XC + idx] = y * sm[OFF_SZ + idx];
    }
    __syncthreads();

    // ---- Stage G: out_proj 128->64 + residual(normed x) -> outb ----
    for (int idx = tid; idx < (cnt >> 1) * 32; idx += 256) {
        int ti0 = (idx >> 5) << 1, cp = (idx & 31) << 1;
        float a00 = sm[OFF_XN + (ti0 + 1) * 64 + cp], a01 = sm[OFF_XN + (ti0 + 1) * 64 + cp + 1];
        float a10 = sm[OFF_XN + (ti0 + 2) * 64 + cp], a11 = sm[OFF_XN + (ti0 + 2) * 64 + cp + 1];
        const float* g0 = &sm[OFF_XC +  ti0      * 128];
        const float* g1 = &sm[OFF_XC + (ti0 + 1) * 128];
        #pragma unroll 8
        for (int d = 0; d < 128; d++) {
            float2 w = *(const float2*)&sm[OFF_WO + d * 64 + cp];
            float v0 = g0[d], v1 = g1[d];
            a00 = fmaf(v0, w.x, a00); a01 = fmaf(v0, w.y, a01);
            a10 = fmaf(v1, w.x, a10); a11 = fmaf(v1, w.y, a11);
        }
        size_t o0 = ((size_t)b * LSEQ + l0 + ti0) * DM + cp;
        *(float2*)&outb[o0]      = make_float2(a00, a01);
        *(float2*)&outb[o0 + DM] = make_float2(a10, a11);
    }
}

extern "C" void kernel_launch(void* const* d_in, const int* in_sizes, int n_in,
                              void* d_out, int out_size) {
    const float* rgb     = (const float*)d_in[0];
    const float* dte     = (const float*)d_in[1];
    const float* conv1_w = (const float*)d_in[2];
    const float* conv1_b = (const float*)d_in[3];
    const float* conv2_w = (const float*)d_in[4];
    const float* conv2_b = (const float*)d_in[5];
    const float* conv3_w = (const float*)d_in[6];
    const float* conv3_b = (const float*)d_in[7];
    const float* norm_w  = (const float*)d_in[8];
    const float* in_proj = (const float*)d_in[9];
    const float* cv_w    = (const float*)d_in[10];
    const float* cv_b    = (const float*)d_in[11];
    const float* xp_w    = (const float*)d_in[12];
    const float* dt_w    = (const float*)d_in[13];
    const float* dt_b    = (const float*)d_in[14];
    const float* A_log   = (const float*)d_in[15];
    const float* Dp      = (const float*)d_in[16];
    const float* op_w    = (const float*)d_in[17];
    float* out = (float*)d_out;
    float* h_final = out + CONV_OUT_ELEMS;

    cudaFuncSetAttribute(rsfm_block_kernel,
                         cudaFuncAttributeMaxDynamicSharedMemorySize, SMEM_BYTES);

    conv_in_kernel<<<128, 256>>>(rgb, conv1_w, conv1_b, 0);
    conv_in_kernel<<<128, 256>>>(dte, conv2_w, conv2_b, 1);

    for (int k = 0; k < 6; k++) {
        rsfm_block_kernel<<<NTILES, 256, SMEM_BYTES>>>(
            k, in_proj, cv_w, cv_b, xp_w, dt_w, dt_b, A_log, Dp, op_w, norm_w, h_final);
    }

    conv_out_kernel<<<128, 256>>>(conv3_w, conv3_b, out);
}

// round 3
// speedup vs baseline: 1.3492x; 1.3492x over previous
#include <cuda_runtime.h>
#include <cuda_bf16.h>
#include <cstddef>

// ---------------------------------------------------------------------------
// RSFM = 2x conv1x1 in  ->  6x fused (rmsnorm + mamba-style block + residual)
//        -> conv1x1 out.   h-update is ELEMENT-WISE over L (no scan); only the
//        depthwise conv1d couples neighboring positions (halo = 1).
// Shapes: B=2, L=4096, d_model=64, d_inner=128, d_state=16, dt_rank=32.
// R2: 512 threads/CTA (16 warps, 25% occ), TT=27 -> 304 CTAs = exactly 2 waves
//     on 152 SMs, fast softplus, per-position work items.
// ---------------------------------------------------------------------------

#define LSEQ   4096
#define DM     64
#define DI     128
#define DS     16
#define TT     27                    // interior positions per tile
#define TPB_   152                   // tiles per batch: 151*27 + 19
#define NTILES (2 * TPB_)            // 304 = 2 * 152 SMs
#define NTHR   512
#define CONV_OUT_ELEMS (2 * 64 * LSEQ)   // 524288

// shared memory layout (float offsets), total 57536 floats = 230144 B
#define OFF_WIN 0        // in_proj^T  [k=64][o=256]
#define OFF_WX  16384    // x_proj^T   [d=128][o=64]
#define OFF_WDT 24576    // dt_proj^T  [r=32][d=128]
#define OFF_WO  28672    // out_proj^T [d=128][c=64]
#define OFF_AS  36864    // A=-exp(A_log), padded [128][17]
#define OFF_CW  39040    // conv1d w [t=3][d=128]
#define OFF_CB  39424
#define OFF_DTB 39552
#define OFF_DP  39680
#define OFF_NW  39808
#define OFF_XN  39872    // rmsnormed input [29][64]
#define OFF_XCR 41728    // raw xc (pre-conv) [29][128]
#define OFF_SZ  45440    // silu(z) [27][128]
#define OFF_XC  48896    // conv+silu xc; later gated y [27][128]
#define OFF_DL  52352    // delta [27][128]
#define OFF_DBC 55808    // x_proj out [27][64]
#define SMEM_FLOATS 57536
#define SMEM_BYTES  (SMEM_FLOATS * 4)

// persistent scratch (device globals; no runtime allocation)
__device__ float g_rgb [2 * LSEQ * DM];
__device__ float g_dte [2 * LSEQ * DM];
__device__ float g_bufA[2 * LSEQ * DM];
__device__ float g_bufB[2 * LSEQ * DM];
__device__ float g_h   [(size_t)2 * LSEQ * DI * DS];   // 64 MB

__device__ __forceinline__ float sigmoidf_(float x) { return 1.f / (1.f + __expf(-x)); }
__device__ __forceinline__ float softplusf_(float x) {
    return (x > 15.f) ? x : __logf(1.f + __expf(x));
}

// ---------------------------------------------------------------------------
// input conv1x1: out[b,l,o] = sum_c x[b,c,l] * w[o,c] + bias[o]
// ---------------------------------------------------------------------------
__global__ __launch_bounds__(256) void conv_in_kernel(
    const float* __restrict__ x, const float* __restrict__ w,
    const float* __restrict__ bias, int which)
{
    __shared__ float xs[64 * 64];   // [cin][p]
    __shared__ float wt[64 * 64];   // [cin][o]
    __shared__ float bs[64];
    float* out = which ? g_dte : g_rgb;

    const int tile = blockIdx.x;      // 128 tiles: b = tile>>6, 64 positions each
    const int b  = tile >> 6;
    const int l0 = (tile & 63) << 6;
    const int tid = threadIdx.x;

    for (int i = tid; i < 4096; i += 256) { int o = i >> 6, c = i & 63; wt[c * 64 + o] = w[i]; }
    if (tid < 64) bs[tid] = bias[tid];
    for (int i = tid; i < 4096; i += 256) {
        int c = i >> 6, p = i & 63;
        xs[i] = x[((size_t)b * 64 + c) * LSEQ + l0 + p];
    }
    __syncthreads();

    const int pg = tid >> 6;          // 4 position groups
    const int o  = tid & 63;
    for (int p = pg; p < 64; p += 4) {
        float acc = bs[o];
        #pragma unroll 8
        for (int c = 0; c < 64; c++) acc = fmaf(xs[c * 64 + p], wt[c * 64 + o], acc);
        out[((size_t)b * LSEQ + l0 + p) * DM + o] = acc;
    }
}

// ---------------------------------------------------------------------------
// final conv1x1: d_out[b,o,l] = sum_c bufB[b,l,c] * w[o,c] + bias[o]  (NCHW)
// ---------------------------------------------------------------------------
__global__ __launch_bounds__(256) void conv_out_kernel(
    const float* __restrict__ w, const float* __restrict__ bias, float* __restrict__ out)
{
    __shared__ float xs[64 * 65];   // [p][c] padded
    __shared__ float ws[64 * 64];   // [o][c]
    __shared__ float bs[64];

    const int tile = blockIdx.x;
    const int b  = tile >> 6;
    const int l0 = (tile & 63) << 6;
    const int tid = threadIdx.x;

    for (int i = tid; i < 4096; i += 256) ws[i] = w[i];
    if (tid < 64) bs[tid] = bias[tid];
    for (int i = tid; i < 4096; i += 256) {
        int p = i >> 6, c = i & 63;
        xs[p * 65 + c] = g_bufB[((size_t)b * LSEQ + l0 + p) * DM + c];
    }
    __syncthreads();

    const int wid = tid >> 5, lane = tid & 31;
    for (int o = wid; o < 64; o += 8)
        for (int p = lane; p < 64; p += 32) {
            float acc = bs[o];
            #pragma unroll 8
            for (int c = 0; c < 64; c++) acc = fmaf(xs[p * 65 + c], ws[o * 64 + c], acc);
            out[((size_t)b * 64 + o) * LSEQ + l0 + p] = acc;
        }
}

// ---------------------------------------------------------------------------
// One fused residual block.  512 threads, one 27-position tile per CTA.
// ---------------------------------------------------------------------------
__global__ __launch_bounds__(NTHR, 1) void rsfm_block_kernel(
    int kblk,
    const float* __restrict__ inpw, const float* __restrict__ cvw, const float* __restrict__ cvb,
    const float* __restrict__ xpw,  const float* __restrict__ dtw, const float* __restrict__ dtb,
    const float* __restrict__ alog, const float* __restrict__ dpw, const float* __restrict__ opw,
    const float* __restrict__ normw, float* __restrict__ h_final)
{
    extern __shared__ float sm[];
    const int tid  = threadIdx.x;
    const int wid  = tid >> 5, lane = tid & 31;

    // ---- load weights (transposed for coalesced matvec reads) ----
    for (int i = tid; i < 256 * 64; i += NTHR) { int o = i >> 6, k = i & 63;  sm[OFF_WIN + k * 256 + o] = inpw[i]; }
    for (int i = tid; i < 64 * 128; i += NTHR) { int o = i >> 7, d = i & 127; sm[OFF_WX  + d * 64  + o] = xpw[i]; }
    for (int i = tid; i < 128 * 32; i += NTHR) { int d = i >> 5, r = i & 31;  sm[OFF_WDT + r * 128 + d] = dtw[i]; }
    for (int i = tid; i < 64 * 128; i += NTHR) { int c = i >> 7, d = i & 127; sm[OFF_WO  + d * 64  + c] = opw[i]; }
    for (int i = tid; i < 128 * 16; i += NTHR) { int d = i >> 4, s = i & 15;  sm[OFF_AS + d * 17 + s] = -__expf(alog[i]); }
    if (tid < 384) { int d = tid / 3, t = tid % 3; sm[OFF_CW + t * 128 + d] = cvw[tid]; }
    if (tid >= 384 && tid < 512) { int j = tid - 384; sm[OFF_CB + j] = cvb[j]; sm[OFF_DTB + j] = dtb[j]; sm[OFF_DP + j] = dpw[j]; }
    if (tid < 64)  sm[OFF_NW + tid] = normw[tid];
    __syncthreads();

    const float* base  = (kblk & 1) ? g_dte : g_rgb;
    const float* prevp = (kblk == 0) ? (const float*)0 : ((kblk & 1) ? g_bufA : g_bufB);
    float*       outb  = (kblk & 1) ? g_bufB : g_bufA;
    const bool   rd_h  = (kblk != 0);
    float*       hout  = (kblk == 5) ? h_final : g_h;

    const int tile = blockIdx.x;
    const int b    = tile / TPB_;
    const int l0   = (tile - b * TPB_) * TT;
    const int cnt  = (TT < LSEQ - l0) ? TT : (LSEQ - l0);     // 27 or 19
    const int ne   = cnt + 2;

    // ---- Stage A: (base + prev) -> rmsnorm -> XN[ne][64] ----
    for (int t = wid; t < ne; t += 16) {
        int l = l0 - 1 + t;
        float x0 = 0.f, x1 = 0.f;
        if (l >= 0 && l < LSEQ) {
            size_t off = ((size_t)b * LSEQ + l) * DM;
            x0 = base[off + lane]; x1 = base[off + lane + 32];
            if (prevp) { x0 += prevp[off + lane]; x1 += prevp[off + lane + 32]; }
        }
        float ss = x0 * x0 + x1 * x1;
        #pragma unroll
        for (int o = 16; o; o >>= 1) ss += __shfl_xor_sync(0xffffffffu, ss, o);
        float inv = rsqrtf(ss * (1.f / 64.f) + 1e-5f);
        sm[OFF_XN + t * 64 + lane]      = x0 * inv * sm[OFF_NW + lane];
        sm[OFF_XN + t * 64 + lane + 32] = x1 * inv * sm[OFF_NW + lane + 32];
    }
    __syncthreads();

    // ---- Stage B: in_proj 64->256.  xc_raw for all slots; silu(z) interior ----
    for (int idx = tid; idx < ne * 64; idx += NTHR) {
        int t = idx >> 6, og = (idx & 63) << 2;
        float a0 = 0.f, a1 = 0.f, a2 = 0.f, a3 = 0.f;
        const float* xn = &sm[OFF_XN + t * 64];
        #pragma unroll 8
        for (int k = 0; k < 64; k++) {
            float x = xn[k];
            float4 w = *(const float4*)&sm[OFF_WIN + k * 256 + og];
            a0 = fmaf(x, w.x, a0); a1 = fmaf(x, w.y, a1);
            a2 = fmaf(x, w.z, a2); a3 = fmaf(x, w.w, a3);
        }
        if (og < 128) {
            *(float4*)&sm[OFF_XCR + t * 128 + og] = make_float4(a0, a1, a2, a3);
        } else if (t >= 1 && t <= cnt) {
            int zi = (t - 1) * 128 + og - 128;
            sm[OFF_SZ + zi + 0] = a0 * sigmoidf_(a0);
            sm[OFF_SZ + zi + 1] = a1 * sigmoidf_(a1);
            sm[OFF_SZ + zi + 2] = a2 * sigmoidf_(a2);
            sm[OFF_SZ + zi + 3] = a3 * sigmoidf_(a3);
        }
    }
    __syncthreads();

    // ---- Stage C: depthwise conv1d (k=3, pad 1) + silu -> XC[cnt][128] ----
    for (int idx = tid; idx < cnt * 128; idx += NTHR) {
        int ti = idx >> 7, d = idx & 127;
        float v = sm[OFF_CB + d];
        v = fmaf(sm[OFF_CW +       d], sm[OFF_XCR +  ti      * 128 + d], v);
        v = fmaf(sm[OFF_CW + 128 + d], sm[OFF_XCR + (ti + 1) * 128 + d], v);
        v = fmaf(sm[OFF_CW + 256 + d], sm[OFF_XCR + (ti + 2) * 128 + d], v);
        sm[OFF_XC + idx] = v * sigmoidf_(v);
    }
    __syncthreads();

    // ---- Stage D: x_proj 128->64 -> DBC[cnt][64]  (1 pos x 2 out per thread) ----
    for (int idx = tid; idx < cnt * 32; idx += NTHR) {
        int ti = idx >> 5, op = (idx & 31) << 1;
        float a0 = 0.f, a1 = 0.f;
        const float* x0 = &sm[OFF_XC + ti * 128];
        #pragma unroll 8
        for (int d = 0; d < 128; d++) {
            float2 w = *(const float2*)&sm[OFF_WX + d * 64 + op];
            float v = x0[d];
            a0 = fmaf(v, w.x, a0); a1 = fmaf(v, w.y, a1);
        }
        *(float2*)&sm[OFF_DBC + ti * 64 + op] = make_float2(a0, a1);
    }
    __syncthreads();

    // ---- Stage E: dt_proj 32->128 + bias + softplus -> DL[cnt][128] ----
    for (int idx = tid; idx < cnt * 64; idx += NTHR) {
        int ti = idx >> 6, dp = (idx & 63) << 1;
        float a0 = sm[OFF_DTB + dp], a1 = sm[OFF_DTB + dp + 1];
        const float* r0 = &sm[OFF_DBC + ti * 64];
        #pragma unroll
        for (int r = 0; r < 32; r++) {
            float2 w = *(const float2*)&sm[OFF_WDT + r * 128 + dp];
            float v = r0[r];
            a0 = fmaf(v, w.x, a0); a1 = fmaf(v, w.y, a1);
        }
        sm[OFF_DL + ti * 128 + dp]     = softplusf_(a0);
        sm[OFF_DL + ti * 128 + dp + 1] = softplusf_(a1);
    }
    __syncthreads();

    // ---- Stage F: SSM h-update + y + gating.  XC[idx] := y * silu(z) ----
    for (int idx = tid; idx < cnt * 128; idx += NTHR) {
        int ti = idx >> 7, d = idx & 127;
        size_t hix = (((size_t)b * LSEQ + l0 + ti) * DI + d) * DS;
        float delta = sm[OFF_DL + idx];
        float xc    = sm[OFF_XC + idx];
        float dx    = delta * xc;
        const float* Bs = &sm[OFF_DBC + ti * 64 + 32];
        const float* Cs = &sm[OFF_DBC + ti * 64 + 48];
        const float* Ar = &sm[OFF_AS + d * 17];
        float4 ho[4];
        if (rd_h) {
            const float4* hp = (const float4*)(g_h + hix);
            ho[0] = hp[0]; ho[1] = hp[1]; ho[2] = hp[2]; ho[3] = hp[3];
        } else {
            ho[0] = ho[1] = ho[2] = ho[3] = make_float4(0.f, 0.f, 0.f, 0.f);
        }
        float y = 0.f;
        float4 hn[4];
        #pragma unroll
        for (int q = 0; q < 4; q++) {
            float* hv = (float*)&hn[q];
            const float* hov = (const float*)&ho[q];
            #pragma unroll
            for (int j = 0; j < 4; j++) {
                int s = q * 4 + j;
                float v = fmaf(__expf(delta * Ar[s]), hov[j], dx * Bs[s]);
                hv[j] = v;
                y = fmaf(v, Cs[s], y);
            }
        }
        float4* hw = (float4*)(hout + hix);
        hw[0] = hn[0]; hw[1] = hn[1]; hw[2] = hn[2]; hw[3] = hn[3];
        y = fmaf(sm[OFF_DP + d], xc, y);
        sm[OFF_XC + idx] = y * sm[OFF_SZ + idx];
    }
    __syncthreads();

    // ---- Stage G: out_proj 128->64 + residual(normed x) -> outb ----
    for (int idx = tid; idx < cnt * 32; idx += NTHR) {
        int ti = idx >> 5, cp = (idx & 31) << 1;
        float a0 = sm[OFF_XN + (ti + 1) * 64 + cp];
        float a1 = sm[OFF_XN + (ti + 1) * 64 + cp + 1];
        const float* g0 = &sm[OFF_XC + ti * 128];
        #pragma unroll 8
        for (int d = 0; d < 128; d++) {
            float2 w = *(const float2*)&sm[OFF_WO + d * 64 + cp];
            float v = g0[d];
            a0 = fmaf(v, w.x, a0); a1 = fmaf(v, w.y, a1);
        }
        size_t o0 = ((size_t)b * LSEQ + l0 + ti) * DM + cp;
        *(float2*)&outb[o0] = make_float2(a0, a1);
    }
}

extern "C" void kernel_launch(void* const* d_in, const int* in_sizes, int n_in,
                              void* d_out, int out_size) {
    const float* rgb     = (const float*)d_in[0];
    const float* dte     = (const float*)d_in[1];
    const float* conv1_w = (const float*)d_in[2];
    const float* conv1_b = (const float*)d_in[3];
    const float* conv2_w = (const float*)d_in[4];
    const float* conv2_b = (const float*)d_in[5];
    const float* conv3_w = (const float*)d_in[6];
    const float* conv3_b = (const float*)d_in[7];
    const float* norm_w  = (const float*)d_in[8];
    const float* in_proj = (const float*)d_in[9];
    const float* cv_w    = (const float*)d_in[10];
    const float* cv_b    = (const float*)d_in[11];
    const float* xp_w    = (const float*)d_in[12];
    const float* dt_w    = (const float*)d_in[13];
    const float* dt_b    = (const float*)d_in[14];
    const float* A_log   = (const float*)d_in[15];
    const float* Dp      = (const float*)d_in[16];
    const float* op_w    = (const float*)d_in[17];
    float* out = (float*)d_out;
    float* h_final = out + CONV_OUT_ELEMS;

    cudaFuncSetAttribute(rsfm_block_kernel,
                         cudaFuncAttributeMaxDynamicSharedMemorySize, SMEM_BYTES);

    conv_in_kernel<<<128, 256>>>(rgb, conv1_w, conv1_b, 0);
    conv_in_kernel<<<128, 256>>>(dte, conv2_w, conv2_b, 1);

    for (int k = 0; k < 6; k++) {
        rsfm_block_kernel<<<NTILES, NTHR, SMEM_BYTES>>>(
            k, in_proj, cv_w, cv_b, xp_w, dt_w, dt_b, A_log, Dp, op_w, norm_w, h_final);
    }

    conv_out_kernel<<<128, 256>>>(conv3_w, conv3_b, out);
}

// round 4
// speedup vs baseline: 1.5763x; 1.1683x over previous
#include <cuda_runtime.h>
#include <cuda_bf16.h>
#include <cstddef>

// ---------------------------------------------------------------------------
// RSFM = 2x conv1x1 in  ->  6x fused (rmsnorm + mamba-style block + residual)
//        -> conv1x1 out.   h-update is ELEMENT-WISE over L (no scan); only the
//        depthwise conv1d couples neighboring positions (halo = 1).
// R3: register-blocked matvecs (4pos x 4out / 2pos x 4out) to cut smem
//     crossbar traffic ~3x (L1 pipe was 82% saturated).
// ---------------------------------------------------------------------------

#define LSEQ   4096
#define DM     64
#define DI     128
#define DS     16
#define TT     27                    // interior positions per tile
#define TPB_   152                   // tiles per batch: 151*27 + 19
#define NTILES (2 * TPB_)            // 304 = 2 * 152 SMs
#define NTHR   512
#define CONV_OUT_ELEMS (2 * 64 * LSEQ)   // 524288

// shared memory layout (float offsets); +128 pad for speculative ragged reads
#define OFF_WIN 0        // in_proj^T  [k=64][o=256]
#define OFF_WX  16384    // x_proj^T   [d=128][o=64]
#define OFF_WDT 24576    // dt_proj^T  [r=32][d=128]
#define OFF_WO  28672    // out_proj^T [d=128][c=64]
#define OFF_AS  36864    // A=-exp(A_log), padded [128][17]
#define OFF_CW  39040    // conv1d w [t=3][d=128]
#define OFF_CB  39424
#define OFF_DTB 39552
#define OFF_DP  39680
#define OFF_NW  39808
#define OFF_XN  39872    // rmsnormed input [29][64]
#define OFF_XCR 41728    // raw xc (pre-conv) [29][128]
#define OFF_SZ  45440    // silu(z) [27][128]
#define OFF_XC  48896    // conv+silu xc; later gated y [27][128]
#define OFF_DL  52352    // delta [27][128]
#define OFF_DBC 55808    // x_proj out [27][64]
#define SMEM_FLOATS (57536 + 128)
#define SMEM_BYTES  (SMEM_FLOATS * 4)

// persistent scratch (device globals; no runtime allocation)
__device__ float g_rgb [2 * LSEQ * DM];
__device__ float g_dte [2 * LSEQ * DM];
__device__ float g_bufA[2 * LSEQ * DM];
__device__ float g_bufB[2 * LSEQ * DM];
__device__ float g_h   [(size_t)2 * LSEQ * DI * DS];   // 64 MB

__device__ __forceinline__ float sigmoidf_(float x) { return 1.f / (1.f + __expf(-x)); }
__device__ __forceinline__ float softplusf_(float x) {
    return (x > 15.f) ? x : __logf(1.f + __expf(x));
}

// ---------------------------------------------------------------------------
// input conv1x1: out[b,l,o] = sum_c x[b,c,l] * w[o,c] + bias[o]
// ---------------------------------------------------------------------------
__global__ __launch_bounds__(256) void conv_in_kernel(
    const float* __restrict__ x, const float* __restrict__ w,
    const float* __restrict__ bias, int which)
{
    __shared__ float xs[64 * 64];   // [cin][p]
    __shared__ float wt[64 * 64];   // [cin][o]
    __shared__ float bs[64];
    float* out = which ? g_dte : g_rgb;

    const int tile = blockIdx.x;      // 128 tiles: b = tile>>6, 64 positions each
    const int b  = tile >> 6;
    const int l0 = (tile & 63) << 6;
    const int tid = threadIdx.x;

    for (int i = tid; i < 4096; i += 256) { int o = i >> 6, c = i & 63; wt[c * 64 + o] = w[i]; }
    if (tid < 64) bs[tid] = bias[tid];
    for (int i = tid; i < 4096; i += 256) {
        int c = i >> 6, p = i & 63;
        xs[i] = x[((size_t)b * 64 + c) * LSEQ + l0 + p];
    }
    __syncthreads();

    const int pg = tid >> 6;          // 4 position groups
    const int o  = tid & 63;
    for (int p = pg; p < 64; p += 4) {
        float acc = bs[o];
        #pragma unroll 8
        for (int c = 0; c < 64; c++) acc = fmaf(xs[c * 64 + p], wt[c * 64 + o], acc);
        out[((size_t)b * LSEQ + l0 + p) * DM + o] = acc;
    }
}

// ---------------------------------------------------------------------------
// final conv1x1: d_out[b,o,l] = sum_c bufB[b,l,c] * w[o,c] + bias[o]  (NCHW)
// ---------------------------------------------------------------------------
__global__ __launch_bounds__(256) void conv_out_kernel(
    const float* __restrict__ w, const float* __restrict__ bias, float* __restrict__ out)
{
    __shared__ float xs[64 * 65];   // [p][c] padded
    __shared__ float ws[64 * 64];   // [o][c]
    __shared__ float bs[64];

    const int tile = blockIdx.x;
    const int b  = tile >> 6;
    const int l0 = (tile & 63) << 6;
    const int tid = threadIdx.x;

    for (int i = tid; i < 4096; i += 256) ws[i] = w[i];
    if (tid < 64) bs[tid] = bias[tid];
    for (int i = tid; i < 4096; i += 256) {
        int p = i >> 6, c = i & 63;
        xs[p * 65 + c] = g_bufB[((size_t)b * LSEQ + l0 + p) * DM + c];
    }
    __syncthreads();

    const int wid = tid >> 5, lane = tid & 31;
    for (int o = wid; o < 64; o += 8)
        for (int p = lane; p < 64; p += 32) {
            float acc = bs[o];
            #pragma unroll 8
            for (int c = 0; c < 64; c++) acc = fmaf(xs[p * 65 + c], ws[o * 64 + c], acc);
            out[((size_t)b * 64 + o) * LSEQ + l0 + p] = acc;
        }
}

// ---------------------------------------------------------------------------
// One fused residual block.  512 threads, one 27-position tile per CTA.
// ---------------------------------------------------------------------------
__global__ __launch_bounds__(NTHR, 1) void rsfm_block_kernel(
    int kblk,
    const float* __restrict__ inpw, const float* __restrict__ cvw, const float* __restrict__ cvb,
    const float* __restrict__ xpw,  const float* __restrict__ dtw, const float* __restrict__ dtb,
    const float* __restrict__ alog, const float* __restrict__ dpw, const float* __restrict__ opw,
    const float* __restrict__ normw, float* __restrict__ h_final)
{
    extern __shared__ float sm[];
    const int tid  = threadIdx.x;
    const int wid  = tid >> 5, lane = tid & 31;

    // ---- load weights (transposed for coalesced matvec reads) ----
    for (int i = tid; i < 256 * 64; i += NTHR) { int o = i >> 6, k = i & 63;  sm[OFF_WIN + k * 256 + o] = inpw[i]; }
    for (int i = tid; i < 64 * 128; i += NTHR) { int o = i >> 7, d = i & 127; sm[OFF_WX  + d * 64  + o] = xpw[i]; }
    for (int i = tid; i < 128 * 32; i += NTHR) { int d = i >> 5, r = i & 31;  sm[OFF_WDT + r * 128 + d] = dtw[i]; }
    for (int i = tid; i < 64 * 128; i += NTHR) { int c = i >> 7, d = i & 127; sm[OFF_WO  + d * 64  + c] = opw[i]; }
    for (int i = tid; i < 128 * 16; i += NTHR) { int d = i >> 4, s = i & 15;  sm[OFF_AS + d * 17 + s] = -__expf(alog[i]); }
    if (tid < 384) { int d = tid / 3, t = tid % 3; sm[OFF_CW + t * 128 + d] = cvw[tid]; }
    if (tid >= 384 && tid < 512) { int j = tid - 384; sm[OFF_CB + j] = cvb[j]; sm[OFF_DTB + j] = dtb[j]; sm[OFF_DP + j] = dpw[j]; }
    if (tid < 64)  sm[OFF_NW + tid] = normw[tid];
    __syncthreads();

    const float* base  = (kblk & 1) ? g_dte : g_rgb;
    const float* prevp = (kblk == 0) ? (const float*)0 : ((kblk & 1) ? g_bufA : g_bufB);
    float*       outb  = (kblk & 1) ? g_bufB : g_bufA;
    const bool   rd_h  = (kblk != 0);
    float*       hout  = (kblk == 5) ? h_final : g_h;

    const int tile = blockIdx.x;
    const int b    = tile / TPB_;
    const int l0   = (tile - b * TPB_) * TT;
    const int cnt  = (TT < LSEQ - l0) ? TT : (LSEQ - l0);     // 27 or 19
    const int ne   = cnt + 2;

    // ---- Stage A: (base + prev) -> rmsnorm -> XN[ne][64] ----
    for (int t = wid; t < ne; t += 16) {
        int l = l0 - 1 + t;
        float x0 = 0.f, x1 = 0.f;
        if (l >= 0 && l < LSEQ) {
            size_t off = ((size_t)b * LSEQ + l) * DM;
            x0 = base[off + lane]; x1 = base[off + lane + 32];
            if (prevp) { x0 += prevp[off + lane]; x1 += prevp[off + lane + 32]; }
        }
        float ss = x0 * x0 + x1 * x1;
        #pragma unroll
        for (int o = 16; o; o >>= 1) ss += __shfl_xor_sync(0xffffffffu, ss, o);
        float inv = rsqrtf(ss * (1.f / 64.f) + 1e-5f);
        sm[OFF_XN + t * 64 + lane]      = x0 * inv * sm[OFF_NW + lane];
        sm[OFF_XN + t * 64 + lane + 32] = x1 * inv * sm[OFF_NW + lane + 32];
    }
    __syncthreads();

    // ---- Stage B: in_proj 64->256, 4 pos x 4 out per thread ----
    {
        const int npg = (ne + 3) >> 2;
        for (int idx = tid; idx < (npg << 6); idx += NTHR) {
            const int pg = idx >> 6;
            const int og = (idx & 63) << 2;
            const int t0 = pg << 2;
            const int pmax = ne - t0;
            float a[4][4];
            #pragma unroll
            for (int p = 0; p < 4; p++) { a[p][0] = a[p][1] = a[p][2] = a[p][3] = 0.f; }
            const float* wb = &sm[OFF_WIN + og];
            const float* xb = &sm[OFF_XN + (t0 << 6)];
            #pragma unroll 4
            for (int k = 0; k < 64; k += 4) {
                float4 w0 = *(const float4*)(wb + (k    ) * 256);
                float4 w1 = *(const float4*)(wb + (k + 1) * 256);
                float4 w2 = *(const float4*)(wb + (k + 2) * 256);
                float4 w3 = *(const float4*)(wb + (k + 3) * 256);
                #pragma unroll
                for (int p = 0; p < 4; p++) {
                    float4 xv = *(const float4*)(xb + (p << 6) + k);
                    a[p][0] = fmaf(xv.x, w0.x, a[p][0]); a[p][1] = fmaf(xv.x, w0.y, a[p][1]);
                    a[p][2] = fmaf(xv.x, w0.z, a[p][2]); a[p][3] = fmaf(xv.x, w0.w, a[p][3]);
                    a[p][0] = fmaf(xv.y, w1.x, a[p][0]); a[p][1] = fmaf(xv.y, w1.y, a[p][1]);
                    a[p][2] = fmaf(xv.y, w1.z, a[p][2]); a[p][3] = fmaf(xv.y, w1.w, a[p][3]);
                    a[p][0] = fmaf(xv.z, w2.x, a[p][0]); a[p][1] = fmaf(xv.z, w2.y, a[p][1]);
                    a[p][2] = fmaf(xv.z, w2.z, a[p][2]); a[p][3] = fmaf(xv.z, w2.w, a[p][3]);
                    a[p][0] = fmaf(xv.w, w3.x, a[p][0]); a[p][1] = fmaf(xv.w, w3.y, a[p][1]);
                    a[p][2] = fmaf(xv.w, w3.z, a[p][2]); a[p][3] = fmaf(xv.w, w3.w, a[p][3]);
                }
            }
            #pragma unroll
            for (int p = 0; p < 4; p++) {
                const int t = t0 + p;
                if (p < pmax) {
                    if (og < 128) {
                        *(float4*)&sm[OFF_XCR + t * 128 + og] = make_float4(a[p][0], a[p][1], a[p][2], a[p][3]);
                    } else if (t >= 1 && t <= cnt) {
                        const int zi = (t - 1) * 128 + og - 128;
                        sm[OFF_SZ + zi + 0] = a[p][0] * sigmoidf_(a[p][0]);
                        sm[OFF_SZ + zi + 1] = a[p][1] * sigmoidf_(a[p][1]);
                        sm[OFF_SZ + zi + 2] = a[p][2] * sigmoidf_(a[p][2]);
                        sm[OFF_SZ + zi + 3] = a[p][3] * sigmoidf_(a[p][3]);
                    }
                }
            }
        }
    }
    __syncthreads();

    // ---- Stage C: depthwise conv1d (k=3, pad 1) + silu -> XC[cnt][128] ----
    for (int idx = tid; idx < cnt * 128; idx += NTHR) {
        int ti = idx >> 7, d = idx & 127;
        float v = sm[OFF_CB + d];
        v = fmaf(sm[OFF_CW +       d], sm[OFF_XCR +  ti      * 128 + d], v);
        v = fmaf(sm[OFF_CW + 128 + d], sm[OFF_XCR + (ti + 1) * 128 + d], v);
        v = fmaf(sm[OFF_CW + 256 + d], sm[OFF_XCR + (ti + 2) * 128 + d], v);
        sm[OFF_XC + idx] = v * sigmoidf_(v);
    }
    __syncthreads();

    const int np2 = (cnt + 1) >> 1;

    // ---- Stage D: x_proj 128->64, 2 pos x 4 out per thread ----
    for (int idx = tid; idx < (np2 << 4); idx += NTHR) {
        const int pg = idx >> 4;
        const int og = (idx & 15) << 2;
        const int t0 = pg << 1;
        float4 a0 = make_float4(0.f, 0.f, 0.f, 0.f);
        float4 a1 = make_float4(0.f, 0.f, 0.f, 0.f);
        const float* wb = &sm[OFF_WX + og];
        const float* x0 = &sm[OFF_XC + t0 * 128];
        #pragma unroll 4
        for (int d = 0; d < 128; d += 4) {
            float4 w0 = *(const float4*)(wb + (d    ) * 64);
            float4 w1 = *(const float4*)(wb + (d + 1) * 64);
            float4 w2 = *(const float4*)(wb + (d + 2) * 64);
            float4 w3 = *(const float4*)(wb + (d + 3) * 64);
            float4 xa = *(const float4*)(x0 + d);
            float4 xc2 = *(const float4*)(x0 + 128 + d);
            a0.x = fmaf(xa.x, w0.x, a0.x); a0.y = fmaf(xa.x, w0.y, a0.y); a0.z = fmaf(xa.x, w0.z, a0.z); a0.w = fmaf(xa.x, w0.w, a0.w);
            a0.x = fmaf(xa.y, w1.x, a0.x); a0.y = fmaf(xa.y, w1.y, a0.y); a0.z = fmaf(xa.y, w1.z, a0.z); a0.w = fmaf(xa.y, w1.w, a0.w);
            a0.x = fmaf(xa.z, w2.x, a0.x); a0.y = fmaf(xa.z, w2.y, a0.y); a0.z = fmaf(xa.z, w2.z, a0.z); a0.w = fmaf(xa.z, w2.w, a0.w);
            a0.x = fmaf(xa.w, w3.x, a0.x); a0.y = fmaf(xa.w, w3.y, a0.y); a0.z = fmaf(xa.w, w3.z, a0.z); a0.w = fmaf(xa.w, w3.w, a0.w);
            a1.x = fmaf(xc2.x, w0.x, a1.x); a1.y = fmaf(xc2.x, w0.y, a1.y); a1.z = fmaf(xc2.x, w0.z, a1.z); a1.w = fmaf(xc2.x, w0.w, a1.w);
            a1.x = fmaf(xc2.y, w1.x, a1.x); a1.y = fmaf(xc2.y, w1.y, a1.y); a1.z = fmaf(xc2.y, w1.z, a1.z); a1.w = fmaf(xc2.y, w1.w, a1.w);
            a1.x = fmaf(xc2.z, w2.x, a1.x); a1.y = fmaf(xc2.z, w2.y, a1.y); a1.z = fmaf(xc2.z, w2.z, a1.z); a1.w = fmaf(xc2.z, w2.w, a1.w);
            a1.x = fmaf(xc2.w, w3.x, a1.x); a1.y = fmaf(xc2.w, w3.y, a1.y); a1.z = fmaf(xc2.w, w3.z, a1.z); a1.w = fmaf(xc2.w, w3.w, a1.w);
        }
        *(float4*)&sm[OFF_DBC + t0 * 64 + og] = a0;
        if (t0 + 1 < cnt) *(float4*)&sm[OFF_DBC + (t0 + 1) * 64 + og] = a1;
    }
    __syncthreads();

    // ---- Stage E: dt_proj 32->128 + bias + softplus, 2 pos x 4 out ----
    for (int idx = tid; idx < (np2 << 5); idx += NTHR) {
        const int pg = idx >> 5;
        const int og = (idx & 31) << 2;
        const int t0 = pg << 1;
        float4 bias = *(const float4*)&sm[OFF_DTB + og];
        float4 a0 = bias, a1 = bias;
        const float* wb = &sm[OFF_WDT + og];
        const float* r0 = &sm[OFF_DBC + t0 * 64];
        #pragma unroll
        for (int r = 0; r < 32; r += 4) {
            float4 w0 = *(const float4*)(wb + (r    ) * 128);
            float4 w1 = *(const float4*)(wb + (r + 1) * 128);
            float4 w2 = *(const float4*)(wb + (r + 2) * 128);
            float4 w3 = *(const float4*)(wb + (r + 3) * 128);
            float4 xa = *(const float4*)(r0 + r);
            float4 xb = *(const float4*)(r0 + 64 + r);
            a0.x = fmaf(xa.x, w0.x, a0.x); a0.y = fmaf(xa.x, w0.y, a0.y); a0.z = fmaf(xa.x, w0.z, a0.z); a0.w = fmaf(xa.x, w0.w, a0.w);
            a0.x = fmaf(xa.y, w1.x, a0.x); a0.y = fmaf(xa.y, w1.y, a0.y); a0.z = fmaf(xa.y, w1.z, a0.z); a0.w = fmaf(xa.y, w1.w, a0.w);
            a0.x = fmaf(xa.z, w2.x, a0.x); a0.y = fmaf(xa.z, w2.y, a0.y); a0.z = fmaf(xa.z, w2.z, a0.z); a0.w = fmaf(xa.z, w2.w, a0.w);
            a0.x = fmaf(xa.w, w3.x, a0.x); a0.y = fmaf(xa.w, w3.y, a0.y); a0.z = fmaf(xa.w, w3.z, a0.z); a0.w = fmaf(xa.w, w3.w, a0.w);
            a1.x = fmaf(xb.x, w0.x, a1.x); a1.y = fmaf(xb.x, w0.y, a1.y); a1.z = fmaf(xb.x, w0.z, a1.z); a1.w = fmaf(xb.x, w0.w, a1.w);
            a1.x = fmaf(xb.y, w1.x, a1.x); a1.y = fmaf(xb.y, w1.y, a1.y); a1.z = fmaf(xb.y, w1.z, a1.z); a1.w = fmaf(xb.y, w1.w, a1.w);
            a1.x = fmaf(xb.z, w2.x, a1.x); a1.y = fmaf(xb.z, w2.y, a1.y); a1.z = fmaf(xb.z, w2.z, a1.z); a1.w = fmaf(xb.z, w2.w, a1.w);
            a1.x = fmaf(xb.w, w3.x, a1.x); a1.y = fmaf(xb.w, w3.y, a1.y); a1.z = fmaf(xb.w, w3.z, a1.z); a1.w = fmaf(xb.w, w3.w, a1.w);
        }
        float* dl0 = &sm[OFF_DL + t0 * 128 + og];
        dl0[0] = softplusf_(a0.x); dl0[1] = softplusf_(a0.y);
        dl0[2] = softplusf_(a0.z); dl0[3] = softplusf_(a0.w);
        if (t0 + 1 < cnt) {
            float* dl1 = &sm[OFF_DL + (t0 + 1) * 128 + og];
            dl1[0] = softplusf_(a1.x); dl1[1] = softplusf_(a1.y);
            dl1[2] = softplusf_(a1.z); dl1[3] = softplusf_(a1.w);
        }
    }
    __syncthreads();

    // ---- Stage F: SSM h-update + y + gating.  XC[idx] := y * silu(z) ----
    for (int idx = tid; idx < cnt * 128; idx += NTHR) {
        int ti = idx >> 7, d = idx & 127;
        size_t hix = (((size_t)b * LSEQ + l0 + ti) * DI + d) * DS;
        float delta = sm[OFF_DL + idx];
        float xc    = sm[OFF_XC + idx];
        float dx    = delta * xc;
        const float* Bs = &sm[OFF_DBC + ti * 64 + 32];
        const float* Cs = &sm[OFF_DBC + ti * 64 + 48];
        const float* Ar = &sm[OFF_AS + d * 17];
        float4 ho[4];
        if (rd_h) {
            const float4* hp = (const float4*)(g_h + hix);
            ho[0] = hp[0]; ho[1] = hp[1]; ho[2] = hp[2]; ho[3] = hp[3];
        } else {
            ho[0] = ho[1] = ho[2] = ho[3] = make_float4(0.f, 0.f, 0.f, 0.f);
        }
        float y = 0.f;
        float4 hn[4];
        #pragma unroll
        for (int q = 0; q < 4; q++) {
            float* hv = (float*)&hn[q];
            const float* hov = (const float*)&ho[q];
            #pragma unroll
            for (int j = 0; j < 4; j++) {
                int s = q * 4 + j;
                float v = fmaf(__expf(delta * Ar[s]), hov[j], dx * Bs[s]);
                hv[j] = v;
                y = fmaf(v, Cs[s], y);
            }
        }
        float4* hw = (float4*)(hout + hix);
        hw[0] = hn[0]; hw[1] = hn[1]; hw[2] = hn[2]; hw[3] = hn[3];
        y = fmaf(sm[OFF_DP + d], xc, y);
        sm[OFF_XC + idx] = y * sm[OFF_SZ + idx];
    }
    __syncthreads();

    // ---- Stage G: out_proj 128->64 + residual(normed x), 2 pos x 4 out ----
    for (int idx = tid; idx < (np2 << 4); idx += NTHR) {
        const int pg = idx >> 4;
        const int og = (idx & 15) << 2;
        const int t0 = pg << 1;
        float4 a0 = *(const float4*)&sm[OFF_XN + (t0 + 1) * 64 + og];
        float4 a1 = *(const float4*)&sm[OFF_XN + (t0 + 2) * 64 + og];
        const float* wb = &sm[OFF_WO + og];
        const float* g0 = &sm[OFF_XC + t0 * 128];
        #pragma unroll 4
        for (int d = 0; d < 128; d += 4) {
            float4 w0 = *(const float4*)(wb + (d    ) * 64);
            float4 w1 = *(const float4*)(wb + (d + 1) * 64);
            float4 w2 = *(const float4*)(wb + (d + 2) * 64);
            float4 w3 = *(const float4*)(wb + (d + 3) * 64);
            float4 xa = *(const float4*)(g0 + d);
            float4 xb = *(const float4*)(g0 + 128 + d);
            a0.x = fmaf(xa.x, w0.x, a0.x); a0.y = fmaf(xa.x, w0.y, a0.y); a0.z = fmaf(xa.x, w0.z, a0.z); a0.w = fmaf(xa.x, w0.w, a0.w);
            a0.x = fmaf(xa.y, w1.x, a0.x); a0.y = fmaf(xa.y, w1.y, a0.y); a0.z = fmaf(xa.y, w1.z, a0.z); a0.w = fmaf(xa.y, w1.w, a0.w);
            a0.x = fmaf(xa.z, w2.x, a0.x); a0.y = fmaf(xa.z, w2.y, a0.y); a0.z = fmaf(xa.z, w2.z, a0.z); a0.w = fmaf(xa.z, w2.w, a0.w);
            a0.x = fmaf(xa.w, w3.x, a0.x); a0.y = fmaf(xa.w, w3.y, a0.y); a0.z = fmaf(xa.w, w3.z, a0.z); a0.w = fmaf(xa.w, w3.w, a0.w);
            a1.x = fmaf(xb.x, w0.x, a1.x); a1.y = fmaf(xb.x, w0.y, a1.y); a1.z = fmaf(xb.x, w0.z, a1.z); a1.w = fmaf(xb.x, w0.w, a1.w);
            a1.x = fmaf(xb.y, w1.x, a1.x); a1.y = fmaf(xb.y, w1.y, a1.y); a1.z = fmaf(xb.y, w1.z, a1.z); a1.w = fmaf(xb.y, w1.w, a1.w);
            a1.x = fmaf(xb.z, w2.x, a1.x); a1.y = fmaf(xb.z, w2.y, a1.y); a1.z = fmaf(xb.z, w2.z, a1.z); a1.w = fmaf(xb.z, w2.w, a1.w);
            a1.x = fmaf(xb.w, w3.x, a1.x); a1.y = fmaf(xb.w, w3.y, a1.y); a1.z = fmaf(xb.w, w3.z, a1.z); a1.w = fmaf(xb.w, w3.w, a1.w);
        }
        size_t o0 = ((size_t)b * LSEQ + l0 + t0) * DM + og;
        *(float4*)&outb[o0] = a0;
        if (t0 + 1 < cnt) *(float4*)&outb[o0 + DM] = a1;
    }
}

extern "C" void kernel_launch(void* const* d_in, const int* in_sizes, int n_in,
                              void* d_out, int out_size) {
    const float* rgb     = (const float*)d_in[0];
    const float* dte     = (const float*)d_in[1];
    const float* conv1_w = (const float*)d_in[2];
    const float* conv1_b = (const float*)d_in[3];
    const float* conv2_w = (const float*)d_in[4];
    const float* conv2_b = (const float*)d_in[5];
    const float* conv3_w = (const float*)d_in[6];
    const float* conv3_b = (const float*)d_in[7];
    const float* norm_w  = (const float*)d_in[8];
    const float* in_proj = (const float*)d_in[9];
    const float* cv_w    = (const float*)d_in[10];
    const float* cv_b    = (const float*)d_in[11];
    const float* xp_w    = (const float*)d_in[12];
    const float* dt_w    = (const float*)d_in[13];
    const float* dt_b    = (const float*)d_in[14];
    const float* A_log   = (const float*)d_in[15];
    const float* Dp      = (const float*)d_in[16];
    const float* op_w    = (const float*)d_in[17];
    float* out = (float*)d_out;
    float* h_final = out + CONV_OUT_ELEMS;

    cudaFuncSetAttribute(rsfm_block_kernel,
                         cudaFuncAttributeMaxDynamicSharedMemorySize, SMEM_BYTES);

    conv_in_kernel<<<128, 256>>>(rgb, conv1_w, conv1_b, 0);
    conv_in_kernel<<<128, 256>>>(dte, conv2_w, conv2_b, 1);

    for (int k = 0; k < 6; k++) {
        rsfm_block_kernel<<<NTILES, NTHR, SMEM_BYTES>>>(
            k, in_proj, cv_w, cv_b, xp_w, dt_w, dt_b, A_log, Dp, op_w, norm_w, h_final);
    }

    conv_out_kernel<<<128, 256>>>(conv3_w, conv3_b, out);
}

// round 6
// speedup vs baseline: 1.6254x; 1.0312x over previous
#include <cuda_runtime.h>
#include <cuda_bf16.h>
#include <cstddef>

// ---------------------------------------------------------------------------
// RSFM = 2x conv1x1 in  ->  6x fused (rmsnorm + mamba-style block + residual)
//        -> conv1x1 out.   h-update is ELEMENT-WISE over L (no scan); only the
//        depthwise conv1d couples neighboring positions (halo = 1).
// R5: fix evict_last encoding (.v4.b64 32-byte vectors), L2-pinned h,
//     8-pos stage-B blocking, 4-pos D/E/G blocking, 768 threads/CTA.
// ---------------------------------------------------------------------------

#define LSEQ   4096
#define DM     64
#define DI     128
#define DS     16
#define TT     27                    // interior positions per tile
#define TPB_   152                   // tiles per batch: 151*27 + 19
#define NTILES (2 * TPB_)            // 304 = 2 * 152 SMs
#define NTHR   768
#define CONV_OUT_ELEMS (2 * 64 * LSEQ)   // 524288

// shared memory layout (float offsets); +128 pad for speculative ragged reads
#define OFF_WIN 0        // in_proj^T  [k=64][o=256]
#define OFF_WX  16384    // x_proj^T   [d=128][o=64]
#define OFF_WDT 24576    // dt_proj^T  [r=32][d=128]
#define OFF_WO  28672    // out_proj^T [d=128][c=64]
#define OFF_AS  36864    // A=-exp(A_log), padded [128][17]
#define OFF_CW  39040    // conv1d w [t=3][d=128]
#define OFF_CB  39424
#define OFF_DTB 39552
#define OFF_DP  39680
#define OFF_NW  39808
#define OFF_XN  39872    // rmsnormed input [29][64]
#define OFF_XCR 41728    // raw xc (pre-conv) [29][128]
#define OFF_SZ  45440    // silu(z) [27][128]
#define OFF_XC  48896    // conv+silu xc; later gated y [27][128]
#define OFF_DL  52352    // delta [27][128]
#define OFF_DBC 55808    // x_proj out [27][64]
#define SMEM_FLOATS (57536 + 128)
#define SMEM_BYTES  (SMEM_FLOATS * 4)

// persistent scratch (device globals; no runtime allocation)
__device__ float g_rgb [2 * LSEQ * DM];
__device__ float g_dte [2 * LSEQ * DM];
__device__ float g_bufA[2 * LSEQ * DM];
__device__ float g_bufB[2 * LSEQ * DM];
__device__ float g_h   [(size_t)2 * LSEQ * DI * DS];   // 64 MB (fits L2: 126MB)

__device__ __forceinline__ float sigmoidf_(float x) { return 1.f / (1.f + __expf(-x)); }
__device__ __forceinline__ float softplusf_(float x) {
    return (x > 15.f) ? x : __logf(1.f + __expf(x));
}

// 32-byte L2-persist loads/stores for the h state (.v4.b64 is the form ptxas
// accepts with .L2::evict_last on sm_103a). Addresses are 32B-aligned.
__device__ __forceinline__ void ld_l2last_32(const float* p, float4& a, float4& b) {
    unsigned long long r0, r1, r2, r3;
    asm("ld.global.L2::evict_last.v4.b64 {%0,%1,%2,%3}, [%4];"
        : "=l"(r0), "=l"(r1), "=l"(r2), "=l"(r3) : "l"(p));
    asm("mov.b64 {%0,%1}, %2;" : "=f"(a.x), "=f"(a.y) : "l"(r0));
    asm("mov.b64 {%0,%1}, %2;" : "=f"(a.z), "=f"(a.w) : "l"(r1));
    asm("mov.b64 {%0,%1}, %2;" : "=f"(b.x), "=f"(b.y) : "l"(r2));
    asm("mov.b64 {%0,%1}, %2;" : "=f"(b.z), "=f"(b.w) : "l"(r3));
}
__device__ __forceinline__ void st_l2last_32(float* p, float4 a, float4 b) {
    unsigned long long r0, r1, r2, r3;
    asm("mov.b64 %0, {%1,%2};" : "=l"(r0) : "f"(a.x), "f"(a.y));
    asm("mov.b64 %0, {%1,%2};" : "=l"(r1) : "f"(a.z), "f"(a.w));
    asm("mov.b64 %0, {%1,%2};" : "=l"(r2) : "f"(b.x), "f"(b.y));
    asm("mov.b64 %0, {%1,%2};" : "=l"(r3) : "f"(b.z), "f"(b.w));
    asm volatile("st.global.L2::evict_last.v4.b64 [%0], {%1,%2,%3,%4};"
                 :: "l"(p), "l"(r0), "l"(r1), "l"(r2), "l"(r3) : "memory");
}

// ---------------------------------------------------------------------------
// input conv1x1: out[b,l,o] = sum_c x[b,c,l] * w[o,c] + bias[o]
// ---------------------------------------------------------------------------
__global__ __launch_bounds__(256) void conv_in_kernel(
    const float* __restrict__ x, const float* __restrict__ w,
    const float* __restrict__ bias, int which)
{
    __shared__ float xs[64 * 64];   // [cin][p]
    __shared__ float wt[64 * 64];   // [cin][o]
    __shared__ float bs[64];
    float* out = which ? g_dte : g_rgb;

    const int tile = blockIdx.x;      // 128 tiles: b = tile>>6, 64 positions each
    const int b  = tile >> 6;
    const int l0 = (tile & 63) << 6;
    const int tid = threadIdx.x;

    for (int i = tid; i < 4096; i += 256) { int o = i >> 6, c = i & 63; wt[c * 64 + o] = w[i]; }
    if (tid < 64) bs[tid] = bias[tid];
    for (int i = tid; i < 4096; i += 256) {
        int c = i >> 6, p = i & 63;
        xs[i] = x[((size_t)b * 64 + c) * LSEQ + l0 + p];
    }
    __syncthreads();

    const int pg = tid >> 6;          // 4 position groups
    const int o  = tid & 63;
    for (int p = pg; p < 64; p += 4) {
        float acc = bs[o];
        #pragma unroll 8
        for (int c = 0; c < 64; c++) acc = fmaf(xs[c * 64 + p], wt[c * 64 + o], acc);
        out[((size_t)b * LSEQ + l0 + p) * DM + o] = acc;
    }
}

// ---------------------------------------------------------------------------
// final conv1x1: d_out[b,o,l] = sum_c bufB[b,l,c] * w[o,c] + bias[o]  (NCHW)
// ---------------------------------------------------------------------------
__global__ __launch_bounds__(256) void conv_out_kernel(
    const float* __restrict__ w, const float* __restrict__ bias, float* __restrict__ out)
{
    __shared__ float xs[64 * 65];   // [p][c] padded
    __shared__ float ws[64 * 64];   // [o][c]
    __shared__ float bs[64];

    const int tile = blockIdx.x;
    const int b  = tile >> 6;
    const int l0 = (tile & 63) << 6;
    const int tid = threadIdx.x;

    for (int i = tid; i < 4096; i += 256) ws[i] = w[i];
    if (tid < 64) bs[tid] = bias[tid];
    for (int i = tid; i < 4096; i += 256) {
        int p = i >> 6, c = i & 63;
        xs[p * 65 + c] = g_bufB[((size_t)b * LSEQ + l0 + p) * DM + c];
    }
    __syncthreads();

    const int wid = tid >> 5, lane = tid & 31;
    for (int o = wid; o < 64; o += 8)
        for (int p = lane; p < 64; p += 32) {
            float acc = bs[o];
            #pragma unroll 8
            for (int c = 0; c < 64; c++) acc = fmaf(xs[p * 65 + c], ws[o * 64 + c], acc);
            out[((size_t)b * 64 + o) * LSEQ + l0 + p] = acc;
        }
}

// ---------------------------------------------------------------------------
// One fused residual block.  768 threads, one 27-position tile per CTA.
// ---------------------------------------------------------------------------
__global__ __launch_bounds__(NTHR, 1) void rsfm_block_kernel(
    int kblk,
    const float* __restrict__ inpw, const float* __restrict__ cvw, const float* __restrict__ cvb,
    const float* __restrict__ xpw,  const float* __restrict__ dtw, const float* __restrict__ dtb,
    const float* __restrict__ alog, const float* __restrict__ dpw, const float* __restrict__ opw,
    const float* __restrict__ normw, float* __restrict__ h_final)
{
    extern __shared__ float sm[];
    const int tid  = threadIdx.x;
    const int wid  = tid >> 5, lane = tid & 31;

    // ---- load weights (transposed for coalesced matvec reads) ----
    for (int i = tid; i < 256 * 64; i += NTHR) { int o = i >> 6, k = i & 63;  sm[OFF_WIN + k * 256 + o] = inpw[i]; }
    for (int i = tid; i < 64 * 128; i += NTHR) { int o = i >> 7, d = i & 127; sm[OFF_WX  + d * 64  + o] = xpw[i]; }
    for (int i = tid; i < 128 * 32; i += NTHR) { int d = i >> 5, r = i & 31;  sm[OFF_WDT + r * 128 + d] = dtw[i]; }
    for (int i = tid; i < 64 * 128; i += NTHR) { int c = i >> 7, d = i & 127; sm[OFF_WO  + d * 64  + c] = opw[i]; }
    for (int i = tid; i < 128 * 16; i += NTHR) { int d = i >> 4, s = i & 15;  sm[OFF_AS + d * 17 + s] = -__expf(alog[i]); }
    if (tid < 384) { int d = tid / 3, t = tid % 3; sm[OFF_CW + t * 128 + d] = cvw[tid]; }
    if (tid >= 384 && tid < 512) { int j = tid - 384; sm[OFF_CB + j] = cvb[j]; sm[OFF_DTB + j] = dtb[j]; sm[OFF_DP + j] = dpw[j]; }
    if (tid < 64)  sm[OFF_NW + tid] = normw[tid];
    __syncthreads();

    const float* base  = (kblk & 1) ? g_dte : g_rgb;
    const float* prevp = (kblk == 0) ? (const float*)0 : ((kblk & 1) ? g_bufA : g_bufB);
    float*       outb  = (kblk & 1) ? g_bufB : g_bufA;
    const bool   rd_h  = (kblk != 0);
    const bool   last  = (kblk == 5);

    const int tile = blockIdx.x;
    const int b    = tile / TPB_;
    const int l0   = (tile - b * TPB_) * TT;
    const int cnt  = (TT < LSEQ - l0) ? TT : (LSEQ - l0);     // 27 or 19
    const int ne   = cnt + 2;

    // ---- Stage A: (base + prev) -> rmsnorm -> XN[ne][64] ----
    for (int t = wid; t < ne; t += (NTHR / 32)) {
        int l = l0 - 1 + t;
        float x0 = 0.f, x1 = 0.f;
        if (l >= 0 && l < LSEQ) {
            size_t off = ((size_t)b * LSEQ + l) * DM;
            x0 = base[off + lane]; x1 = base[off + lane + 32];
            if (prevp) { x0 += prevp[off + lane]; x1 += prevp[off + lane + 32]; }
        }
        float ss = x0 * x0 + x1 * x1;
        #pragma unroll
        for (int o = 16; o; o >>= 1) ss += __shfl_xor_sync(0xffffffffu, ss, o);
        float inv = rsqrtf(ss * (1.f / 64.f) + 1e-5f);
        sm[OFF_XN + t * 64 + lane]      = x0 * inv * sm[OFF_NW + lane];
        sm[OFF_XN + t * 64 + lane + 32] = x1 * inv * sm[OFF_NW + lane + 32];
    }
    __syncthreads();

    // ---- Stage B: in_proj 64->256, 8 pos x 4 out per thread ----
    {
        const int npg = (ne + 7) >> 3;          // 4 (or 3)
        for (int idx = tid; idx < (npg << 6); idx += NTHR) {
            const int pg = idx >> 6;
            const int og = (idx & 63) << 2;
            const int t0 = pg << 3;
            const int pmax = ne - t0;
            float4 acc[8];
            #pragma unroll
            for (int p = 0; p < 8; p++) acc[p] = make_float4(0.f, 0.f, 0.f, 0.f);
            const float* wb = &sm[OFF_WIN + og];
            const float* xb = &sm[OFF_XN + (t0 << 6)];
            #pragma unroll 2
            for (int k = 0; k < 64; k += 4) {
                float4 w0 = *(const float4*)(wb + (k    ) * 256);
                float4 w1 = *(const float4*)(wb + (k + 1) * 256);
                float4 w2 = *(const float4*)(wb + (k + 2) * 256);
                float4 w3 = *(const float4*)(wb + (k + 3) * 256);
                #pragma unroll
                for (int p = 0; p < 8; p++) {
                    float4 xv = *(const float4*)(xb + (p << 6) + k);
                    acc[p].x = fmaf(xv.x, w0.x, acc[p].x); acc[p].y = fmaf(xv.x, w0.y, acc[p].y);
                    acc[p].z = fmaf(xv.x, w0.z, acc[p].z); acc[p].w = fmaf(xv.x, w0.w, acc[p].w);
                    acc[p].x = fmaf(xv.y, w1.x, acc[p].x); acc[p].y = fmaf(xv.y, w1.y, acc[p].y);
                    acc[p].z = fmaf(xv.y, w1.z, acc[p].z); acc[p].w = fmaf(xv.y, w1.w, acc[p].w);
                    acc[p].x = fmaf(xv.z, w2.x, acc[p].x); acc[p].y = fmaf(xv.z, w2.y, acc[p].y);
                    acc[p].z = fmaf(xv.z, w2.z, acc[p].z); acc[p].w = fmaf(xv.z, w2.w, acc[p].w);
                    acc[p].x = fmaf(xv.w, w3.x, acc[p].x); acc[p].y = fmaf(xv.w, w3.y, acc[p].y);
                    acc[p].z = fmaf(xv.w, w3.z, acc[p].z); acc[p].w = fmaf(xv.w, w3.w, acc[p].w);
                }
            }
            #pragma unroll
            for (int p = 0; p < 8; p++) {
                const int t = t0 + p;
                if (p < pmax) {
                    if (og < 128) {
                        *(float4*)&sm[OFF_XCR + t * 128 + og] = acc[p];
                    } else if (t >= 1 && t <= cnt) {
                        const int zi = (t - 1) * 128 + og - 128;
                        sm[OFF_SZ + zi + 0] = acc[p].x * sigmoidf_(acc[p].x);
                        sm[OFF_SZ + zi + 1] = acc[p].y * sigmoidf_(acc[p].y);
                        sm[OFF_SZ + zi + 2] = acc[p].z * sigmoidf_(acc[p].z);
                        sm[OFF_SZ + zi + 3] = acc[p].w * sigmoidf_(acc[p].w);
                    }
                }
            }
        }
    }
    __syncthreads();

    // ---- Stage C: depthwise conv1d (k=3, pad 1) + silu -> XC[cnt][128] ----
    for (int idx = tid; idx < cnt * 128; idx += NTHR) {
        int ti = idx >> 7, d = idx & 127;
        float v = sm[OFF_CB + d];
        v = fmaf(sm[OFF_CW +       d], sm[OFF_XCR +  ti      * 128 + d], v);
        v = fmaf(sm[OFF_CW + 128 + d], sm[OFF_XCR + (ti + 1) * 128 + d], v);
        v = fmaf(sm[OFF_CW + 256 + d], sm[OFF_XCR + (ti + 2) * 128 + d], v);
        sm[OFF_XC + idx] = v * sigmoidf_(v);
    }
    __syncthreads();

    const int np4 = (cnt + 3) >> 2;   // 7 (or 5)

    // ---- Stage D: x_proj 128->64, 4 pos x 4 out per thread ----
    for (int idx = tid; idx < (np4 << 4); idx += NTHR) {
        const int pg = idx >> 4;
        const int og = (idx & 15) << 2;
        const int t0 = pg << 2;
        float4 acc[4];
        #pragma unroll
        for (int p = 0; p < 4; p++) acc[p] = make_float4(0.f, 0.f, 0.f, 0.f);
        const float* wb = &sm[OFF_WX + og];
        const float* x0 = &sm[OFF_XC + t0 * 128];
        #pragma unroll 4
        for (int d = 0; d < 128; d += 4) {
            float4 w0 = *(const float4*)(wb + (d    ) * 64);
            float4 w1 = *(const float4*)(wb + (d + 1) * 64);
            float4 w2 = *(const float4*)(wb + (d + 2) * 64);
            float4 w3 = *(const float4*)(wb + (d + 3) * 64);
            #pragma unroll
            for (int p = 0; p < 4; p++) {
                float4 xv = *(const float4*)(x0 + p * 128 + d);
                acc[p].x = fmaf(xv.x, w0.x, acc[p].x); acc[p].y = fmaf(xv.x, w0.y, acc[p].y);
                acc[p].z = fmaf(xv.x, w0.z, acc[p].z); acc[p].w = fmaf(xv.x, w0.w, acc[p].w);
                acc[p].x = fmaf(xv.y, w1.x, acc[p].x); acc[p].y = fmaf(xv.y, w1.y, acc[p].y);
                acc[p].z = fmaf(xv.y, w1.z, acc[p].z); acc[p].w = fmaf(xv.y, w1.w, acc[p].w);
                acc[p].x = fmaf(xv.z, w2.x, acc[p].x); acc[p].y = fmaf(xv.z, w2.y, acc[p].y);
                acc[p].z = fmaf(xv.z, w2.z, acc[p].z); acc[p].w = fmaf(xv.z, w2.w, acc[p].w);
                acc[p].x = fmaf(xv.w, w3.x, acc[p].x); acc[p].y = fmaf(xv.w, w3.y, acc[p].y);
                acc[p].z = fmaf(xv.w, w3.z, acc[p].z); acc[p].w = fmaf(xv.w, w3.w, acc[p].w);
            }
        }
        #pragma unroll
        for (int p = 0; p < 4; p++)
            if (t0 + p < cnt) *(float4*)&sm[OFF_DBC + (t0 + p) * 64 + og] = acc[p];
    }
    __syncthreads();

    // ---- Stage E: dt_proj 32->128 + bias + softplus, 4 pos x 4 out ----
    for (int idx = tid; idx < (np4 << 5); idx += NTHR) {
        const int pg = idx >> 5;
        const int og = (idx & 31) << 2;
        const int t0 = pg << 2;
        float4 bias = *(const float4*)&sm[OFF_DTB + og];
        float4 acc[4];
        #pragma unroll
        for (int p = 0; p < 4; p++) acc[p] = bias;
        const float* wb = &sm[OFF_WDT + og];
        const float* r0 = &sm[OFF_DBC + t0 * 64];
        #pragma unroll
        for (int r = 0; r < 32; r += 4) {
            float4 w0 = *(const float4*)(wb + (r    ) * 128);
            float4 w1 = *(const float4*)(wb + (r + 1) * 128);
            float4 w2 = *(const float4*)(wb + (r + 2) * 128);
            float4 w3 = *(const float4*)(wb + (r + 3) * 128);
            #pragma unroll
            for (int p = 0; p < 4; p++) {
                float4 xv = *(const float4*)(r0 + p * 64 + r);
                acc[p].x = fmaf(xv.x, w0.x, acc[p].x); acc[p].y = fmaf(xv.x, w0.y, acc[p].y);
                acc[p].z = fmaf(xv.x, w0.z, acc[p].z); acc[p].w = fmaf(xv.x, w0.w, acc[p].w);
                acc[p].x = fmaf(xv.y, w1.x, acc[p].x); acc[p].y = fmaf(xv.y, w1.y, acc[p].y);
                acc[p].z = fmaf(xv.y, w1.z, acc[p].z); acc[p].w = fmaf(xv.y, w1.w, acc[p].w);
                acc[p].x = fmaf(xv.z, w2.x, acc[p].x); acc[p].y = fmaf(xv.z, w2.y, acc[p].y);
                acc[p].z = fmaf(xv.z, w2.z, acc[p].z); acc[p].w = fmaf(xv.z, w2.w, acc[p].w);
                acc[p].x = fmaf(xv.w, w3.x, acc[p].x); acc[p].y = fmaf(xv.w, w3.y, acc[p].y);
                acc[p].z = fmaf(xv.w, w3.z, acc[p].z); acc[p].w = fmaf(xv.w, w3.w, acc[p].w);
            }
        }
        #pragma unroll
        for (int p = 0; p < 4; p++) {
            if (t0 + p < cnt) {
                float* dl = &sm[OFF_DL + (t0 + p) * 128 + og];
                dl[0] = softplusf_(acc[p].x); dl[1] = softplusf_(acc[p].y);
                dl[2] = softplusf_(acc[p].z); dl[3] = softplusf_(acc[p].w);
            }
        }
    }
    __syncthreads();

    // ---- Stage F: SSM h-update + y + gating.  XC[idx] := y * silu(z) ----
    for (int idx = tid; idx < cnt * 128; idx += NTHR) {
        int ti = idx >> 7, d = idx & 127;
        size_t hix = (((size_t)b * LSEQ + l0 + ti) * DI + d) * DS;
        float delta = sm[OFF_DL + idx];
        float xc    = sm[OFF_XC + idx];
        float dx    = delta * xc;
        const float* Bs = &sm[OFF_DBC + ti * 64 + 32];
        const float* Cs = &sm[OFF_DBC + ti * 64 + 48];
        const float* Ar = &sm[OFF_AS + d * 17];
        float4 ho[4];
        if (rd_h) {
            ld_l2last_32(g_h + hix,     ho[0], ho[1]);
            ld_l2last_32(g_h + hix + 8, ho[2], ho[3]);
        } else {
            ho[0] = ho[1] = ho[2] = ho[3] = make_float4(0.f, 0.f, 0.f, 0.f);
        }
        float y = 0.f;
        float4 hn[4];
        #pragma unroll
        for (int q = 0; q < 4; q++) {
            float* hv = (float*)&hn[q];
            const float* hov = (const float*)&ho[q];
            #pragma unroll
            for (int j = 0; j < 4; j++) {
                int s = q * 4 + j;
                float v = fmaf(__expf(delta * Ar[s]), hov[j], dx * Bs[s]);
                hv[j] = v;
                y = fmaf(v, Cs[s], y);
            }
        }
        if (last) {
            float4* hw = (float4*)(h_final + hix);
            hw[0] = hn[0]; hw[1] = hn[1]; hw[2] = hn[2]; hw[3] = hn[3];
        } else {
            st_l2last_32(g_h + hix,     hn[0], hn[1]);
            st_l2last_32(g_h + hix + 8, hn[2], hn[3]);
        }
        y = fmaf(sm[OFF_DP + d], xc, y);
        sm[OFF_XC + idx] = y * sm[OFF_SZ + idx];
    }
    __syncthreads();

    // ---- Stage G: out_proj 128->64 + residual(normed x), 4 pos x 4 out ----
    for (int idx = tid; idx < (np4 << 4); idx += NTHR) {
        const int pg = idx >> 4;
        const int og = (idx & 15) << 2;
        const int t0 = pg << 2;
        float4 acc[4];
        #pragma unroll
        for (int p = 0; p < 4; p++) acc[p] = *(const float4*)&sm[OFF_XN + (t0 + p + 1) * 64 + og];
        const float* wb = &sm[OFF_WO + og];
        const float* g0 = &sm[OFF_XC + t0 * 128];
        #pragma unroll 4
        for (int d = 0; d < 128; d += 4) {
            float4 w0 = *(const float4*)(wb + (d    ) * 64);
            float4 w1 = *(const float4*)(wb + (d + 1) * 64);
            float4 w2 = *(const float4*)(wb + (d + 2) * 64);
            float4 w3 = *(const float4*)(wb + (d + 3) * 64);
            #pragma unroll
            for (int p = 0; p < 4; p++) {
                float4 xv = *(const float4*)(g0 + p * 128 + d);
                acc[p].x = fmaf(xv.x, w0.x, acc[p].x); acc[p].y = fmaf(xv.x, w0.y, acc[p].y);
                acc[p].z = fmaf(xv.x, w0.z, acc[p].z); acc[p].w = fmaf(xv.x, w0.w, acc[p].w);
                acc[p].x = fmaf(xv.y, w1.x, acc[p].x); acc[p].y = fmaf(xv.y, w1.y, acc[p].y);
                acc[p].z = fmaf(xv.y, w1.z, acc[p].z); acc[p].w = fmaf(xv.y, w1.w, acc[p].w);
                acc[p].x = fmaf(xv.z, w2.x, acc[p].x); acc[p].y = fmaf(xv.z, w2.y, acc[p].y);
                acc[p].z = fmaf(xv.z, w2.z, acc[p].z); acc[p].w = fmaf(xv.z, w2.w, acc[p].w);
                acc[p].x = fmaf(xv.w, w3.x, acc[p].x); acc[p].y = fmaf(xv.w, w3.y, acc[p].y);
                acc[p].z = fmaf(xv.w, w3.z, acc[p].z); acc[p].w = fmaf(xv.w, w3.w, acc[p].w);
            }
        }
        #pragma unroll
        for (int p = 0; p < 4; p++) {
            if (t0 + p < cnt) {
                size_t o0 = ((size_t)b * LSEQ + l0 + t0 + p) * DM + og;
                *(float4*)&outb[o0] = acc[p];
            }
        }
    }
}

extern "C" void kernel_launch(void* const* d_in, const int* in_sizes, int n_in,
                              void* d_out, int out_size) {
    const float* rgb     = (const float*)d_in[0];
    const float* dte     = (const float*)d_in[1];
    const float* conv1_w = (const float*)d_in[2];
    const float* conv1_b = (const float*)d_in[3];
    const float* conv2_w = (const float*)d_in[4];
    const float* conv2_b = (const float*)d_in[5];
    const float* conv3_w = (const float*)d_in[6];
    const float* conv3_b = (const float*)d_in[7];
    const float* norm_w  = (const float*)d_in[8];
    const float* in_proj = (const float*)d_in[9];
    const float* cv_w    = (const float*)d_in[10];
    const float* cv_b    = (const float*)d_in[11];
    const float* xp_w    = (const float*)d_in[12];
    const float* dt_w    = (const float*)d_in[13];
    const float* dt_b    = (const float*)d_in[14];
    const float* A_log   = (const float*)d_in[15];
    const float* Dp      = (const float*)d_in[16];
    const float* op_w    = (const float*)d_in[17];
    float* out = (float*)d_out;
    float* h_final = out + CONV_OUT_ELEMS;

    cudaFuncSetAttribute(rsfm_block_kernel,
                         cudaFuncAttributeMaxDynamicSharedMemorySize, SMEM_BYTES);

    conv_in_kernel<<<128, 256>>>(rgb, conv1_w, conv1_b, 0);
    conv_in_kernel<<<128, 256>>>(dte, conv2_w, conv2_b, 1);

    for (int k = 0; k < 6; k++) {
        rsfm_block_kernel<<<NTILES, NTHR, SMEM_BYTES>>>(
            k, in_proj, cv_w, cv_b, xp_w, dt_w, dt_b, A_log, Dp, op_w, norm_w, h_final);
    }

    conv_out_kernel<<<128, 256>>>(conv3_w, conv3_b, out);
}

// round 8
// speedup vs baseline: 1.6717x; 1.0285x over previous
#include <cuda_runtime.h>
#include <cuda_bf16.h>
#include <cstddef>

// ---------------------------------------------------------------------------
// RSFM = 2x conv1x1 in  ->  6x fused (rmsnorm + mamba-style block + residual)
//        -> conv1x1 out.   h-update is ELEMENT-WISE over L (no scan); only the
//        depthwise conv1d couples neighboring positions (halo = 1).
// R6: CTA split into two independent 384-thread halves (named barriers) to
//     overlap stage pipelines; rebalanced blocking (B 4p4o, D/E/G 2p4o);
//     L2 prefetch of h; DL aliased onto dead XCR buffer.
// ---------------------------------------------------------------------------

#define LSEQ   4096
#define DM     64
#define DI     128
#define DS     16
#define TT     27                    // interior positions per tile
#define HHALF  14                    // positions owned by half 0 (half1 = cnt-14)
#define TPB_   152                   // tiles per batch: 151*27 + 19
#define NTILES (2 * TPB_)            // 304 = 2 * 152 SMs
#define NTHR   768
#define NHALF  384
#define CONV_OUT_ELEMS (2 * 64 * LSEQ)   // 524288

// shared memory layout (float offsets)
#define OFF_WIN 0        // in_proj^T  [k=64][o=256]
#define OFF_WX  16384    // x_proj^T   [d=128][o=64]
#define OFF_WDT 24576    // dt_proj^T  [r=32][d=128]
#define OFF_WO  28672    // out_proj^T [d=128][c=64]
#define OFF_AS  36864    // A=-exp(A_log), padded [128][17]
#define OFF_CW  39040    // conv1d w [t=3][d=128]
#define OFF_CB  39424
#define OFF_DTB 39552
#define OFF_DP  39680
#define OFF_NW  39808
// per-half activation regions (half stride in comments)
#define OFF_XN  39872    // [2][16][64]   rmsnormed input  (stride 1024)
#define OFF_XCR 41920    // [2][16][128]  raw xc; later aliased by DL (stride 2048)
#define OFF_SZ  46016    // [2][14][128]  silu(z)          (stride 1792)
#define OFF_XC  49600    // [2][14][128]  conv+silu xc; later gated y
#define OFF_DBC 53184    // [2][14][64]   x_proj out       (stride 896)
#define SMEM_FLOATS (54976 + 64)
#define SMEM_BYTES  (SMEM_FLOATS * 4)
#define OFF_DL  OFF_XCR  // alias: XCR dead after stage C

// persistent scratch (device globals; no runtime allocation)
__device__ float g_rgb [2 * LSEQ * DM];
__device__ float g_dte [2 * LSEQ * DM];
__device__ float g_bufA[2 * LSEQ * DM];
__device__ float g_bufB[2 * LSEQ * DM];
__device__ float g_h   [(size_t)2 * LSEQ * DI * DS];   // 64 MB

__device__ __forceinline__ float sigmoidf_(float x) { return 1.f / (1.f + __expf(-x)); }
__device__ __forceinline__ float softplusf_(float x) {
    return (x > 15.f) ? x : __logf(1.f + __expf(x));
}

// 32-byte L2-persist loads/stores for the h state
__device__ __forceinline__ void ld_l2last_32(const float* p, float4& a, float4& b) {
    unsigned long long r0, r1, r2, r3;
    asm("ld.global.L2::evict_last.v4.b64 {%0,%1,%2,%3}, [%4];"
        : "=l"(r0), "=l"(r1), "=l"(r2), "=l"(r3) : "l"(p));
    asm("mov.b64 {%0,%1}, %2;" : "=f"(a.x), "=f"(a.y) : "l"(r0));
    asm("mov.b64 {%0,%1}, %2;" : "=f"(a.z), "=f"(a.w) : "l"(r1));
    asm("mov.b64 {%0,%1}, %2;" : "=f"(b.x), "=f"(b.y) : "l"(r2));
    asm("mov.b64 {%0,%1}, %2;" : "=f"(b.z), "=f"(b.w) : "l"(r3));
}
__device__ __forceinline__ void st_l2last_32(float* p, float4 a, float4 b) {
    unsigned long long r0, r1, r2, r3;
    asm("mov.b64 %0, {%1,%2};" : "=l"(r0) : "f"(a.x), "f"(a.y));
    asm("mov.b64 %0, {%1,%2};" : "=l"(r1) : "f"(a.z), "f"(a.w));
    asm("mov.b64 %0, {%1,%2};" : "=l"(r2) : "f"(b.x), "f"(b.y));
    asm("mov.b64 %0, {%1,%2};" : "=l"(r3) : "f"(b.z), "f"(b.w));
    asm volatile("st.global.L2::evict_last.v4.b64 [%0], {%1,%2,%3,%4};"
                 :: "l"(p), "l"(r0), "l"(r1), "l"(r2), "l"(r3) : "memory");
}
__device__ __forceinline__ void barrier_half(int h) {
    asm volatile("bar.sync %0, %1;" :: "r"(h + 1), "r"(NHALF) : "memory");
}

// ---------------------------------------------------------------------------
// input conv1x1
// ---------------------------------------------------------------------------
__global__ __launch_bounds__(256) void conv_in_kernel(
    const float* __restrict__ x, const float* __restrict__ w,
    const float* __restrict__ bias, int which)
{
    __shared__ float xs[64 * 64];
    __shared__ float wt[64 * 64];
    __shared__ float bs[64];
    float* out = which ? g_dte : g_rgb;

    const int tile = blockIdx.x;
    const int b  = tile >> 6;
    const int l0 = (tile & 63) << 6;
    const int tid = threadIdx.x;

    for (int i = tid; i < 4096; i += 256) { int o = i >> 6, c = i & 63; wt[c * 64 + o] = w[i]; }
    if (tid < 64) bs[tid] = bias[tid];
    for (int i = tid; i < 4096; i += 256) {
        int c = i >> 6, p = i & 63;
        xs[i] = x[((size_t)b * 64 + c) * LSEQ + l0 + p];
    }
    __syncthreads();

    const int pg = tid >> 6;
    const int o  = tid & 63;
    for (int p = pg; p < 64; p += 4) {
        float acc = bs[o];
        #pragma unroll 8
        for (int c = 0; c < 64; c++) acc = fmaf(xs[c * 64 + p], wt[c * 64 + o], acc);
        out[((size_t)b * LSEQ + l0 + p) * DM + o] = acc;
    }
}

// ---------------------------------------------------------------------------
// final conv1x1 (NCHW out)
// ---------------------------------------------------------------------------
__global__ __launch_bounds__(256) void conv_out_kernel(
    const float* __restrict__ w, const float* __restrict__ bias, float* __restrict__ out)
{
    __shared__ float xs[64 * 65];
    __shared__ float ws[64 * 64];
    __shared__ float bs[64];

    const int tile = blockIdx.x;
    const int b  = tile >> 6;
    const int l0 = (tile & 63) << 6;
    const int tid = threadIdx.x;

    for (int i = tid; i < 4096; i += 256) ws[i] = w[i];
    if (tid < 64) bs[tid] = bias[tid];
    for (int i = tid; i < 4096; i += 256) {
        int p = i >> 6, c = i & 63;
        xs[p * 65 + c] = g_bufB[((size_t)b * LSEQ + l0 + p) * DM + c];
    }
    __syncthreads();

    const int wid = tid >> 5, lane = tid & 31;
    for (int o = wid; o < 64; o += 8)
        for (int p = lane; p < 64; p += 32) {
            float acc = bs[o];
            #pragma unroll 8
            for (int c = 0; c < 64; c++) acc = fmaf(xs[p * 65 + c], ws[o * 64 + c], acc);
            out[((size_t)b * 64 + o) * LSEQ + l0 + p] = acc;
        }
}

// ---------------------------------------------------------------------------
// One fused residual block. 768 threads = 2 independent 384-thread halves.
// ---------------------------------------------------------------------------
__global__ __launch_bounds__(NTHR, 1) void rsfm_block_kernel(
    int kblk,
    const float* __restrict__ inpw, const float* __restrict__ cvw, const float* __restrict__ cvb,
    const float* __restrict__ xpw,  const float* __restrict__ dtw, const float* __restrict__ dtb,
    const float* __restrict__ alog, const float* __restrict__ dpw, const float* __restrict__ opw,
    const float* __restrict__ normw, float* __restrict__ h_final)
{
    extern __shared__ float sm[];
    const int tid  = threadIdx.x;

    const float* base  = (kblk & 1) ? g_dte : g_rgb;
    const float* prevp = (kblk == 0) ? (const float*)0 : ((kblk & 1) ? g_bufA : g_bufB);
    float*       outb  = (kblk & 1) ? g_bufB : g_bufA;
    const bool   rd_h  = (kblk != 0);
    const bool   last  = (kblk == 5);

    const int tile = blockIdx.x;
    const int b    = tile / TPB_;
    const int l0   = (tile - b * TPB_) * TT;
    const int cnt  = (TT < LSEQ - l0) ? TT : (LSEQ - l0);     // 27 or 19

    // L2 prefetch of this tile's h (overlaps with weight staging)
    if (rd_h) {
        for (int idx = tid; idx < cnt * 128; idx += 2 * NTHR) {
            size_t hix = (((size_t)b * LSEQ + l0 + (idx >> 7)) * DI + (idx & 127)) * DS;
            asm volatile("prefetch.global.L2 [%0];" :: "l"(g_h + hix));
        }
    }

    // ---- stage weights into smem (full CTA) ----
    for (int i = tid; i < 256 * 64; i += NTHR) { int o = i >> 6, k = i & 63;  sm[OFF_WIN + k * 256 + o] = inpw[i]; }
    for (int i = tid; i < 64 * 128; i += NTHR) { int o = i >> 7, d = i & 127; sm[OFF_WX  + d * 64  + o] = xpw[i]; }
    for (int i = tid; i < 128 * 32; i += NTHR) { int d = i >> 5, r = i & 31;  sm[OFF_WDT + r * 128 + d] = dtw[i]; }
    for (int i = tid; i < 64 * 128; i += NTHR) { int c = i >> 7, d = i & 127; sm[OFF_WO  + d * 64  + c] = opw[i]; }
    for (int i = tid; i < 128 * 16; i += NTHR) { int d = i >> 4, s = i & 15;  sm[OFF_AS + d * 17 + s] = -__expf(alog[i]); }
    if (tid < 384) { int d = tid / 3, t = tid % 3; sm[OFF_CW + t * 128 + d] = cvw[tid]; }
    if (tid >= 384 && tid < 512) { int j = tid - 384; sm[OFF_CB + j] = cvb[j]; sm[OFF_DTB + j] = dtb[j]; sm[OFF_DP + j] = dpw[j]; }
    if (tid < 64)  sm[OFF_NW + tid] = normw[tid];
    __syncthreads();

    // ---- half decomposition: independent pipelines from here on ----
    const int h    = (tid >= NHALF) ? 1 : 0;
    const int gt   = tid - h * NHALF;             // 0..383
    const int gw   = gt >> 5, lane = gt & 31;     // 12 warps per half
    const int p0   = h * HHALF;                   // first interior pos of this half
    const int cnth = h ? (cnt - HHALF) : HHALF;   // 14 / 13 (or 5 ragged)
    const int neh  = cnth + 2;

    float* XN  = &sm[OFF_XN  + h * 1024];
    float* XCR = &sm[OFF_XCR + h * 2048];
    float* SZ  = &sm[OFF_SZ  + h * 1792];
    float* XC  = &sm[OFF_XC  + h * 1792];
    float* DL  = &sm[OFF_DL  + h * 2048];  // alias of XCR
    float* DBC = &sm[OFF_DBC + h * 896];

    // ---- Stage A: (base + prev) -> rmsnorm -> XN[neh][64] ----
    for (int t = gw; t < neh; t += 12) {
        int l = l0 + p0 - 1 + t;
        float x0 = 0.f, x1 = 0.f;
        if (l >= 0 && l < LSEQ) {
            size_t off = ((size_t)b * LSEQ + l) * DM;
            x0 = base[off + lane]; x1 = base[off + lane + 32];
            if (prevp) { x0 += prevp[off + lane]; x1 += prevp[off + lane + 32]; }
        }
        float ss = x0 * x0 + x1 * x1;
        #pragma unroll
        for (int o = 16; o; o >>= 1) ss += __shfl_xor_sync(0xffffffffu, ss, o);
        float inv = rsqrtf(ss * (1.f / 64.f) + 1e-5f);
        XN[t * 64 + lane]      = x0 * inv * sm[OFF_NW + lane];
        XN[t * 64 + lane + 32] = x1 * inv * sm[OFF_NW + lane + 32];
    }
    barrier_half(h);

    // ---- Stage B: in_proj 64->256, 4 pos x 4 out per thread ----
    {
        const int npg = (neh + 3) >> 2;       // <= 4
        for (int idx = gt; idx < (npg << 6); idx += NHALF) {
            const int pg = idx >> 6;
            const int og = (idx & 63) << 2;
            const int t0 = pg << 2;
            const int pmax = neh - t0;
            float4 acc[4];
            #pragma unroll
            for (int p = 0; p < 4; p++) acc[p] = make_float4(0.f, 0.f, 0.f, 0.f);
            const float* wb = &sm[OFF_WIN + og];
            const float* xb = &XN[t0 << 6];
            #pragma unroll 4
            for (int k = 0; k < 64; k += 4) {
                float4 w0 = *(const float4*)(wb + (k    ) * 256);
                float4 w1 = *(const float4*)(wb + (k + 1) * 256);
                float4 w2 = *(const float4*)(wb + (k + 2) * 256);
                float4 w3 = *(const float4*)(wb + (k + 3) * 256);
                #pragma unroll
                for (int p = 0; p < 4; p++) {
                    float4 xv = *(const float4*)(xb + (p << 6) + k);
                    acc[p].x = fmaf(xv.x, w0.x, acc[p].x); acc[p].y = fmaf(xv.x, w0.y, acc[p].y);
                    acc[p].z = fmaf(xv.x, w0.z, acc[p].z); acc[p].w = fmaf(xv.x, w0.w, acc[p].w);
                    acc[p].x = fmaf(xv.y, w1.x, acc[p].x); acc[p].y = fmaf(xv.y, w1.y, acc[p].y);
                    acc[p].z = fmaf(xv.y, w1.z, acc[p].z); acc[p].w = fmaf(xv.y, w1.w, acc[p].w);
                    acc[p].x = fmaf(xv.z, w2.x, acc[p].x); acc[p].y = fmaf(xv.z, w2.y, acc[p].y);
                    acc[p].z = fmaf(xv.z, w2.z, acc[p].z); acc[p].w = fmaf(xv.z, w2.w, acc[p].w);
                    acc[p].x = fmaf(xv.w, w3.x, acc[p].x); acc[p].y = fmaf(xv.w, w3.y, acc[p].y);
                    acc[p].z = fmaf(xv.w, w3.z, acc[p].z); acc[p].w = fmaf(xv.w, w3.w, acc[p].w);
                }
            }
            #pragma unroll
            for (int p = 0; p < 4; p++) {
                const int t = t0 + p;
                if (p < pmax) {
                    if (og < 128) {
                        *(float4*)&XCR[t * 128 + og] = acc[p];
                    } else if (t >= 1 && t <= cnth) {
                        const int zi = (t - 1) * 128 + og - 128;
                        SZ[zi + 0] = acc[p].x * sigmoidf_(acc[p].x);
                        SZ[zi + 1] = acc[p].y * sigmoidf_(acc[p].y);
                        SZ[zi + 2] = acc[p].z * sigmoidf_(acc[p].z);
                        SZ[zi + 3] = acc[p].w * sigmoidf_(acc[p].w);
                    }
                }
            }
        }
    }
    barrier_half(h);

    // ---- Stage C: depthwise conv1d (k=3, pad 1) + silu -> XC[cnth][128] ----
    for (int idx = gt; idx < cnth * 128; idx += NHALF) {
        int ti = idx >> 7, d = idx & 127;
        float v = sm[OFF_CB + d];
        v = fmaf(sm[OFF_CW +       d], XCR[ ti      * 128 + d], v);
        v = fmaf(sm[OFF_CW + 128 + d], XCR[(ti + 1) * 128 + d], v);
        v = fmaf(sm[OFF_CW + 256 + d], XCR[(ti + 2) * 128 + d], v);
        XC[idx] = v * sigmoidf_(v);
    }
    barrier_half(h);

    const int np2 = (cnth + 1) >> 1;

    // ---- Stage D: x_proj 128->64, 2 pos x 4 out per thread ----
    for (int idx = gt; idx < (np2 << 4); idx += NHALF) {
        const int pg = idx >> 4;
        const int og = (idx & 15) << 2;
        const int t0 = pg << 1;
        float4 a0 = make_float4(0.f, 0.f, 0.f, 0.f);
        float4 a1 = make_float4(0.f, 0.f, 0.f, 0.f);
        const float* wb = &sm[OFF_WX + og];
        const float* x0 = &XC[t0 * 128];
        #pragma unroll 4
        for (int d = 0; d < 128; d += 4) {
            float4 w0 = *(const float4*)(wb + (d    ) * 64);
            float4 w1 = *(const float4*)(wb + (d + 1) * 64);
            float4 w2 = *(const float4*)(wb + (d + 2) * 64);
            float4 w3 = *(const float4*)(wb + (d + 3) * 64);
            float4 xa = *(const float4*)(x0 + d);
            float4 xb2 = *(const float4*)(x0 + 128 + d);
            a0.x = fmaf(xa.x, w0.x, a0.x); a0.y = fmaf(xa.x, w0.y, a0.y); a0.z = fmaf(xa.x, w0.z, a0.z); a0.w = fmaf(xa.x, w0.w, a0.w);
            a0.x = fmaf(xa.y, w1.x, a0.x); a0.y = fmaf(xa.y, w1.y, a0.y); a0.z = fmaf(xa.y, w1.z, a0.z); a0.w = fmaf(xa.y, w1.w, a0.w);
            a0.x = fmaf(xa.z, w2.x, a0.x); a0.y = fmaf(xa.z, w2.y, a0.y); a0.z = fmaf(xa.z, w2.z, a0.z); a0.w = fmaf(xa.z, w2.w, a0.w);
            a0.x = fmaf(xa.w, w3.x, a0.x); a0.y = fmaf(xa.w, w3.y, a0.y); a0.z = fmaf(xa.w, w3.z, a0.z); a0.w = fmaf(xa.w, w3.w, a0.w);
            a1.x = fmaf(xb2.x, w0.x, a1.x); a1.y = fmaf(xb2.x, w0.y, a1.y); a1.z = fmaf(xb2.x, w0.z, a1.z); a1.w = fmaf(xb2.x, w0.w, a1.w);
            a1.x = fmaf(xb2.y, w1.x, a1.x); a1.y = fmaf(xb2.y, w1.y, a1.y); a1.z = fmaf(xb2.y, w1.z, a1.z); a1.w = fmaf(xb2.y, w1.w, a1.w);
            a1.x = fmaf(xb2.z, w2.x, a1.x); a1.y = fmaf(xb2.z, w2.y, a1.y); a1.z = fmaf(xb2.z, w2.z, a1.z); a1.w = fmaf(xb2.z, w2.w, a1.w);
            a1.x = fmaf(xb2.w, w3.x, a1.x); a1.y = fmaf(xb2.w, w3.y, a1.y); a1.z = fmaf(xb2.w, w3.z, a1.z); a1.w = fmaf(xb2.w, w3.w, a1.w);
        }
        *(float4*)&DBC[t0 * 64 + og] = a0;
        if (t0 + 1 < cnth) *(float4*)&DBC[(t0 + 1) * 64 + og] = a1;
    }
    barrier_half(h);

    // ---- Stage E: dt_proj 32->128 + bias + softplus, 2 pos x 4 out ----
    for (int idx = gt; idx < (np2 << 5); idx += NHALF) {
        const int pg = idx >> 5;
        const int og = (idx & 31) << 2;
        const int t0 = pg << 1;
        float4 bias = *(const float4*)&sm[OFF_DTB + og];
        float4 a0 = bias, a1 = bias;
        const float* wb = &sm[OFF_WDT + og];
        const float* r0 = &DBC[t0 * 64];
        #pragma unroll
        for (int r = 0; r < 32; r += 4) {
            float4 w0 = *(const float4*)(wb + (r    ) * 128);
            float4 w1 = *(const float4*)(wb + (r + 1) * 128);
            float4 w2 = *(const float4*)(wb + (r + 2) * 128);
            float4 w3 = *(const float4*)(wb + (r + 3) * 128);
            float4 xa = *(const float4*)(r0 + r);
            float4 xb2 = *(const float4*)(r0 + 64 + r);
            a0.x = fmaf(xa.x, w0.x, a0.x); a0.y = fmaf(xa.x, w0.y, a0.y); a0.z = fmaf(xa.x, w0.z, a0.z); a0.w = fmaf(xa.x, w0.w, a0.w);
            a0.x = fmaf(xa.y, w1.x, a0.x); a0.y = fmaf(xa.y, w1.y, a0.y); a0.z = fmaf(xa.y, w1.z, a0.z); a0.w = fmaf(xa.y, w1.w, a0.w);
            a0.x = fmaf(xa.z, w2.x, a0.x); a0.y = fmaf(xa.z, w2.y, a0.y); a0.z = fmaf(xa.z, w2.z, a0.z); a0.w = fmaf(xa.z, w2.w, a0.w);
            a0.x = fmaf(xa.w, w3.x, a0.x); a0.y = fmaf(xa.w, w3.y, a0.y); a0.z = fmaf(xa.w, w3.z, a0.z); a0.w = fmaf(xa.w, w3.w, a0.w);
            a1.x = fmaf(xb2.x, w0.x, a1.x); a1.y = fmaf(xb2.x, w0.y, a1.y); a1.z = fmaf(xb2.x, w0.z, a1.z); a1.w = fmaf(xb2.x, w0.w, a1.w);
            a1.x = fmaf(xb2.y, w1.x, a1.x); a1.y = fmaf(xb2.y, w1.y, a1.y); a1.z = fmaf(xb2.y, w1.z, a1.z); a1.w = fmaf(xb2.y, w1.w, a1.w);
            a1.x = fmaf(xb2.z, w2.x, a1.x); a1.y = fmaf(xb2.z, w2.y, a1.y); a1.z = fmaf(xb2.z, w2.z, a1.z); a1.w = fmaf(xb2.z, w2.w, a1.w);
            a1.x = fmaf(xb2.w, w3.x, a1.x); a1.y = fmaf(xb2.w, w3.y, a1.y); a1.z = fmaf(xb2.w, w3.z, a1.z); a1.w = fmaf(xb2.w, w3.w, a1.w);
        }
        float* dl0 = &DL[t0 * 128 + og];
        dl0[0] = softplusf_(a0.x); dl0[1] = softplusf_(a0.y);
        dl0[2] = softplusf_(a0.z); dl0[3] = softplusf_(a0.w);
        if (t0 + 1 < cnth) {
            float* dl1 = &DL[(t0 + 1) * 128 + og];
            dl1[0] = softplusf_(a1.x); dl1[1] = softplusf_(a1.y);
            dl1[2] = softplusf_(a1.z); dl1[3] = softplusf_(a1.w);
        }
    }
    barrier_half(h);

    // ---- Stage F: SSM h-update + y + gating.  XC[idx] := y * silu(z) ----
    for (int idx = gt; idx < cnth * 128; idx += NHALF) {
        int ti = idx >> 7, d = idx & 127;
        size_t hix = (((size_t)b * LSEQ + l0 + p0 + ti) * DI + d) * DS;
        float delta = DL[idx];
        float xc    = XC[idx];
        float dx    = delta * xc;
        const float* Bs = &DBC[ti * 64 + 32];
        const float* Cs = &DBC[ti * 64 + 48];
        const float* Ar = &sm[OFF_AS + d * 17];
        float4 ho[4];
        if (rd_h) {
            ld_l2last_32(g_h + hix,     ho[0], ho[1]);
            ld_l2last_32(g_h + hix + 8, ho[2], ho[3]);
        } else {
            ho[0] = ho[1] = ho[2] = ho[3] = make_float4(0.f, 0.f, 0.f, 0.f);
        }
        float y = 0.f;
        float4 hn[4];
        #pragma unroll
        for (int q = 0; q < 4; q++) {
            float* hv = (float*)&hn[q];
            const float* hov = (const float*)&ho[q];
            #pragma unroll
            for (int j = 0; j < 4; j++) {
                int s = q * 4 + j;
                float v = fmaf(__expf(delta * Ar[s]), hov[j], dx * Bs[s]);
                hv[j] = v;
                y = fmaf(v, Cs[s], y);
            }
        }
        if (last) {
            float4* hw = (float4*)(h_final + hix);
            hw[0] = hn[0]; hw[1] = hn[1]; hw[2] = hn[2]; hw[3] = hn[3];
        } else {
            st_l2last_32(g_h + hix,     hn[0], hn[1]);
            st_l2last_32(g_h + hix + 8, hn[2], hn[3]);
        }
        y = fmaf(sm[OFF_DP + d], xc, y);
        XC[idx] = y * SZ[idx];
    }
    barrier_half(h);

    // ---- Stage G: out_proj 128->64 + residual(normed x), 2 pos x 4 out ----
    for (int idx = gt; idx < (np2 << 4); idx += NHALF) {
        const int pg = idx >> 4;
        const int og = (idx & 15) << 2;
        const int t0 = pg << 1;
        float4 a0 = *(const float4*)&XN[(t0 + 1) * 64 + og];
        float4 a1 = *(const float4*)&XN[(t0 + 2) * 64 + og];
        const float* wb = &sm[OFF_WO + og];
        const float* g0 = &XC[t0 * 128];
        #pragma unroll 4
        for (int d = 0; d < 128; d += 4) {
            float4 w0 = *(const float4*)(wb + (d    ) * 64);
            float4 w1 = *(const float4*)(wb + (d + 1) * 64);
            float4 w2 = *(const float4*)(wb + (d + 2) * 64);
            float4 w3 = *(const float4*)(wb + (d + 3) * 64);
            float4 xa = *(const float4*)(g0 + d);
            float4 xb2 = *(const float4*)(g0 + 128 + d);
            a0.x = fmaf(xa.x, w0.x, a0.x); a0.y = fmaf(xa.x, w0.y, a0.y); a0.z = fmaf(xa.x, w0.z, a0.z); a0.w = fmaf(xa.x, w0.w, a0.w);
            a0.x = fmaf(xa.y, w1.x, a0.x); a0.y = fmaf(xa.y, w1.y, a0.y); a0.z = fmaf(xa.y, w1.z, a0.z); a0.w = fmaf(xa.y, w1.w, a0.w);
            a0.x = fmaf(xa.z, w2.x, a0.x); a0.y = fmaf(xa.z, w2.y, a0.y); a0.z = fmaf(xa.z, w2.z, a0.z); a0.w = fmaf(xa.z, w2.w, a0.w);
            a0.x = fmaf(xa.w, w3.x, a0.x); a0.y = fmaf(xa.w, w3.y, a0.y); a0.z = fmaf(xa.w, w3.z, a0.z); a0.w = fmaf(xa.w, w3.w, a0.w);
            a1.x = fmaf(xb2.x, w0.x, a1.x); a1.y = fmaf(xb2.x, w0.y, a1.y); a1.z = fmaf(xb2.x, w0.z, a1.z); a1.w = fmaf(xb2.x, w0.w, a1.w);
            a1.x = fmaf(xb2.y, w1.x, a1.x); a1.y = fmaf(xb2.y, w1.y, a1.y); a1.z = fmaf(xb2.y, w1.z, a1.z); a1.w = fmaf(xb2.y, w1.w, a1.w);
            a1.x = fmaf(xb2.z, w2.x, a1.x); a1.y = fmaf(xb2.z, w2.y, a1.y); a1.z = fmaf(xb2.z, w2.z, a1.z); a1.w = fmaf(xb2.z, w2.w, a1.w);
            a1.x = fmaf(xb2.w, w3.x, a1.x); a1.y = fmaf(xb2.w, w3.y, a1.y); a1.z = fmaf(xb2.w, w3.z, a1.z); a1.w = fmaf(xb2.w, w3.w, a1.w);
        }
        size_t o0 = ((size_t)b * LSEQ + l0 + p0 + t0) * DM + og;
        *(float4*)&outb[o0] = a0;
        if (t0 + 1 < cnth) *(float4*)&outb[o0 + DM] = a1;
    }
}

extern "C" void kernel_launch(void* const* d_in, const int* in_sizes, int n_in,
                              void* d_out, int out_size) {
    const float* rgb     = (const float*)d_in[0];
    const float* dte     = (const float*)d_in[1];
    const float* conv1_w = (const float*)d_in[2];
    const float* conv1_b = (const float*)d_in[3];
    const float* conv2_w = (const float*)d_in[4];
    const float* conv2_b = (const float*)d_in[5];
    const float* conv3_w = (const float*)d_in[6];
    const float* conv3_b = (const float*)d_in[7];
    const float* norm_w  = (const float*)d_in[8];
    const float* in_proj = (const float*)d_in[9];
    const float* cv_w    = (const float*)d_in[10];
    const float* cv_b    = (const float*)d_in[11];
    const float* xp_w    = (const float*)d_in[12];
    const float* dt_w    = (const float*)d_in[13];
    const float* dt_b    = (const float*)d_in[14];
    const float* A_log   = (const float*)d_in[15];
    const float* Dp      = (const float*)d_in[16];
    const float* op_w    = (const float*)d_in[17];
    float* out = (float*)d_out;
    float* h_final = out + CONV_OUT_ELEMS;

    cudaFuncSetAttribute(rsfm_block_kernel,
                         cudaFuncAttributeMaxDynamicSharedMemorySize, SMEM_BYTES);

    conv_in_kernel<<<128, 256>>>(rgb, conv1_w, conv1_b, 0);
    conv_in_kernel<<<128, 256>>>(dte, conv2_w, conv2_b, 1);

    for (int k = 0; k < 6; k++) {
        rsfm_block_kernel<<<NTILES, NTHR, SMEM_BYTES>>>(
            k, in_proj, cv_w, cv_b, xp_w, dt_w, dt_b, A_log, Dp, op_w, norm_w, h_final);
    }

    conv_out_kernel<<<128, 256>>>(conv3_w, conv3_b, out);
}